// round 9
// baseline (speedup 1.0000x reference)
#include <cuda_runtime.h>
#include <math.h>
#include <stdint.h>

constexpr int H = 256;
constexpr int B = 4;
constexpr int S = 128;
constexpr int T = 128;

typedef unsigned long long ull;

// Scratch (device globals — no allocation allowed)
__device__ float g_pre_x[(size_t)B * S * T * H];
__device__ float g_pre_y[(size_t)B * S * T * H];
__device__ float g_hx  [(size_t)B * S * T * H];
__device__ float g_hy  [(size_t)B * S * T * H];
__device__ float g_psx [(size_t)B * S * H];
__device__ float g_psy [(size_t)B * T * H];

// ---------------- packed f32x2 + PTX helpers ----------------
__device__ __forceinline__ void ffma2(ull& d, ull a, ull b) {
    asm("fma.rn.f32x2 %0, %1, %2, %0;" : "+l"(d) : "l"(a), "l"(b));
}
__device__ __forceinline__ float hsum2(ull v) {
    float lo, hi;
    asm("mov.b64 {%0, %1}, %2;" : "=f"(lo), "=f"(hi) : "l"(v));
    return lo + hi;
}
__device__ __forceinline__ ull packf2(float a, float b) {
    ull r; asm("mov.b64 %0, {%1, %2};" : "=l"(r) : "f"(a), "f"(b)); return r;
}
__device__ __forceinline__ uint32_t smem_u32(const void* p) {
    uint32_t a;
    asm("{ .reg .u64 t; cvta.to.shared.u64 t, %1; cvt.u32.u64 %0, t; }" : "=r"(a) : "l"(p));
    return a;
}
__device__ __forceinline__ uint32_t mapa_u32(uint32_t addr, uint32_t rank) {
    uint32_t r;
    asm("mapa.shared::cluster.u32 %0, %1, %2;" : "=r"(r) : "r"(addr), "r"(rank));
    return r;
}
__device__ __forceinline__ void st_cluster_b64(uint32_t addr, ull v) {
    asm volatile("st.shared::cluster.b64 [%0], %1;" :: "r"(addr), "l"(v) : "memory");
}
__device__ __forceinline__ void cp_async16(uint32_t dst, const void* src) {
    asm volatile("cp.async.cg.shared.global [%0], [%1], 16;" :: "r"(dst), "l"(src) : "memory");
}
__device__ __forceinline__ void cp_commit() {
    asm volatile("cp.async.commit_group;" ::: "memory");
}
template <int N>
__device__ __forceinline__ void cp_wait() {
    asm volatile("cp.async.wait_group %0;" :: "n"(N) : "memory");
}
#define CLUSTER_SYNC() do { \
    asm volatile("barrier.cluster.arrive.aligned;" ::: "memory"); \
    asm volatile("barrier.cluster.wait.aligned;" ::: "memory"); \
} while (0)

// Accurate tanh regardless of --use_fast_math
__device__ __forceinline__ float my_tanh(float x) {
    float ax = fabsf(x);
    float e  = expf(-2.0f * ax);
    float t  = (1.0f - e) / (1.0f + e);
    return x < 0.0f ? -t : t;
}

// ---------------------------------------------------------------------------
// Prepass GEMM: C[m,n] = sum_k A[m,k]*W[n,k] + b1[n] + b2[n]
// K=N=256. BM=BN=128, BK=32, 256 thr, 8m x 8n per thread (k-split f32x2 accs).
// cp.async double-buffered; SMEM stride 32 with chunk XOR-swizzle (q ^= row&7).
// ---------------------------------------------------------------------------
constexpr int GEMM_SMEM = 2 * 2 * 128 * 32 * 4;   // 65536 B

__global__ void __launch_bounds__(256, 1) gemm128_bias(
    const float* __restrict__ A, const float* __restrict__ W,
    const float* __restrict__ b1, const float* __restrict__ b2,
    float* __restrict__ C)
{
    extern __shared__ float smp[];
    // layout: As[2][4096], Bs[2][4096]  (floats)
    const int m0  = blockIdx.x << 7;
    const int n0  = blockIdx.y << 7;
    const int tid = threadIdx.x;
    const int tx  = tid & 15;         // n lanes (cols tx + 16j)
    const int ty  = tid >> 4;         // m lanes (rows ty + 16i)

    // cp.async staging map: row = tid&127, chunks cq..cq+3 (cq = 0 or 4)
    const int crow = tid & 127;
    const int cq   = (tid >> 7) << 2;
    const int csw  = crow & 7;
    const float* Ag = A + (size_t)(m0 + crow) * H;
    const float* Wg = W + (size_t)(n0 + crow) * H;
    const uint32_t smpU = smem_u32(smp);
    const uint32_t aRow = smpU + (uint32_t)(crow * 32) * 4;
    const uint32_t bRow = smpU + (uint32_t)(8192 + crow * 32) * 4;

    auto stage = [&](int buf, int kb) {
        const uint32_t bo = (uint32_t)buf * 16384u;
        #pragma unroll
        for (int s = 0; s < 4; s++) {
            int q = cq + s;
            uint32_t sw = (uint32_t)((q ^ csw) << 4);
            cp_async16(aRow + bo + sw, Ag + kb + (q << 2));
            cp_async16(bRow + bo + sw, Wg + kb + (q << 2));
        }
        cp_commit();
    };

    stage(0, 0);
    stage(1, 32);

    ull acc[8][8] = {};
    const int swA = ty & 7;
    const int swB = tx & 7;

    for (int c = 0; c < 8; c++) {
        if (c < 7) cp_wait<1>(); else cp_wait<0>();
        __syncthreads();

        const float* ab = smp + (c & 1) * 4096 + ty * 32;
        const float* bb = smp + 8192 + (c & 1) * 4096 + tx * 32;

        #pragma unroll
        for (int kk = 0; kk < 32; kk += 4) {
            const int qa = kk >> 2;
            ulonglong2 Av[8], Wv[8];
            #pragma unroll
            for (int i = 0; i < 8; i++)
                Av[i] = *(const ulonglong2*)(ab + (i << 9) + ((qa ^ swA) << 2));
            #pragma unroll
            for (int j = 0; j < 8; j++)
                Wv[j] = *(const ulonglong2*)(bb + (j << 9) + ((qa ^ swB) << 2));
            #pragma unroll
            for (int i = 0; i < 8; i++)
                #pragma unroll
                for (int j = 0; j < 8; j++)
                    ffma2(acc[i][j], Av[i].x, Wv[j].x);
            #pragma unroll
            for (int i = 0; i < 8; i++)
                #pragma unroll
                for (int j = 0; j < 8; j++)
                    ffma2(acc[i][j], Av[i].y, Wv[j].y);
        }
        __syncthreads();
        if (c < 6) stage(c & 1, (c + 2) << 5);
    }

    float bv[8];
    #pragma unroll
    for (int j = 0; j < 8; j++) {
        int n = n0 + tx + (j << 4);
        bv[j] = b1[n] + b2[n];
    }
    #pragma unroll
    for (int i = 0; i < 8; i++) {
        float* Cp = C + (size_t)(m0 + ty + (i << 4)) * H + n0 + tx;
        #pragma unroll
        for (int j = 0; j < 8; j++)
            Cp[j << 4] = hsum2(acc[i][j]) + bv[j];
    }
}

// ---------------------------------------------------------------------------
// Recurrence: diagonal chains, cluster-2, W resident in SMEM (kpair-interleaved),
// state double-buffered in SMEM, DSMEM exchange, one cluster.sync per step.
// grid (2, 64), cluster (2,1,1), 256 threads (2 warps/SMSP for latency hiding).
// Warp = 16 chains x 16 cols; lane = 4 chains x 2 cols.
// ---------------------------------------------------------------------------
struct RP {
    const float* W;                       // [256n][256k] row-major (this path+depth)
    const float* pre; long p_sb, p_sstep, p_sj;
    float*       out; long o_sb, o_sstep, o_sj;
    int diag;                             // 1 = x-path (j advances with step)
};

constexpr int W2_FLOATS = 128 * 260;          // [kpair][2*col(128)+pad]
constexpr int AS_FLOATS = 16 * 260;           // [chain][k(256)+pad]
constexpr int RECUR_SMEM = (W2_FLOATS + 2 * AS_FLOATS) * 4;   // 166400 B

__global__ void __launch_bounds__(256, 1) __cluster_dims__(2, 1, 1)
recur2(RP X, RP Y)
{
    extern __shared__ float sm[];
    float* W2  = sm;                       // [128 kpairs][260]
    float* As0 = sm + W2_FLOATS;           // [16][260]
    float* As1 = As0 + AS_FLOATS;

    const int rank  = blockIdx.x;          // cluster rank 0/1
    const int clid  = blockIdx.y;
    const int path  = clid >> 5;
    const RP  P     = path ? Y : X;
    const int grp   = clid & 31;
    const int b     = grp >> 3;
    const int dbase = (grp & 7) << 4;

    const int tid  = threadIdx.x;
    const int w    = tid >> 5;             // warp 0..7 (16 cols each)
    const int lane = tid & 31;
    const int cg   = lane >> 3;            // chain group 0..3
    const int cls  = lane & 7;             // col lane 0..7
    const int c0L  = (w << 4) + (cls << 1);   // local cols c0L, c0L+1
    const int gc0  = (rank << 7) + c0L;

    int lc[4], dch[4];
    #pragma unroll
    for (int i = 0; i < 4; i++) { lc[i] = cg + (i << 2); dch[i] = dbase + lc[i]; }

    // ---- fill W2: W2[p][2c..2c+1] = {W[c][2p], W[c][2p+1]}, c = local col ----
    {
        const float* Wg = P.W + (size_t)(rank << 7) * H;
        for (int idx = tid; idx < 128 * 64; idx += 256) {
            int c = idx >> 6, kq = (idx & 63) << 2;
            float4 v = *(const float4*)&Wg[(size_t)c * H + kq];
            int p0 = kq >> 1;
            *(float2*)&W2[p0 * 260 + (c << 1)]       = make_float2(v.x, v.y);
            *(float2*)&W2[(p0 + 1) * 260 + (c << 1)] = make_float2(v.z, v.w);
        }
    }

    const uint32_t as0U  = smem_u32(As0);
    const uint32_t peerU = mapa_u32(as0U, rank ^ 1);
    const float* wBase = W2 + (c0L << 1);

    for (int st = 0; st < 128; st++) {
        int jc[4];
        #pragma unroll
        for (int i = 0; i < 4; i++)
            jc[i] = P.diag ? ((dch[i] + st) & 127) : dch[i];

        // prefetch pre (consumed after GEMM; DRAM latency hidden)
        float2 pv[4];
        #pragma unroll
        for (int i = 0; i < 4; i++)
            pv[i] = *(const float2*)(P.pre + b * P.p_sb + st * P.p_sstep
                                     + jc[i] * P.p_sj + gc0);

        ull acc[4][2] = {};
        if (st > 0) {
            const float* Ac = (st & 1) ? As1 : As0;   // buffer written at st-1
            const float* a0 = Ac + lc[0] * 260;
            const float* a1 = Ac + lc[1] * 260;
            const float* a2 = Ac + lc[2] * 260;
            const float* a3 = Ac + lc[3] * 260;
            #pragma unroll 8
            for (int k = 0; k < 256; k += 4) {
                ulonglong2 A0 = *(const ulonglong2*)(a0 + k);
                ulonglong2 A1 = *(const ulonglong2*)(a1 + k);
                ulonglong2 A2 = *(const ulonglong2*)(a2 + k);
                ulonglong2 A3 = *(const ulonglong2*)(a3 + k);
                const float* wp = wBase + (k >> 1) * 260;
                ulonglong2 L0 = *(const ulonglong2*)(wp);          // kpair p
                ulonglong2 L1 = *(const ulonglong2*)(wp + 260);    // kpair p+1
                ffma2(acc[0][0], A0.x, L0.x); ffma2(acc[0][1], A0.x, L0.y);
                ffma2(acc[1][0], A1.x, L0.x); ffma2(acc[1][1], A1.x, L0.y);
                ffma2(acc[2][0], A2.x, L0.x); ffma2(acc[2][1], A2.x, L0.y);
                ffma2(acc[3][0], A3.x, L0.x); ffma2(acc[3][1], A3.x, L0.y);
                ffma2(acc[0][0], A0.y, L1.x); ffma2(acc[0][1], A0.y, L1.y);
                ffma2(acc[1][0], A1.y, L1.x); ffma2(acc[1][1], A1.y, L1.y);
                ffma2(acc[2][0], A2.y, L1.x); ffma2(acc[2][1], A2.y, L1.y);
                ffma2(acc[3][0], A3.y, L1.x); ffma2(acc[3][1], A3.y, L1.y);
            }
        }

        float h[4][2];
        #pragma unroll
        for (int i = 0; i < 4; i++) {
            h[i][0] = my_tanh(hsum2(acc[i][0]) + pv[i].x);
            h[i][1] = my_tanh(hsum2(acc[i][1]) + pv[i].y);
        }

        // publish state for step st+1: peer SMEM (DSMEM) first, then own
        if (st < 127) {
            float* An = (st & 1) ? As0 : As1;
            const uint32_t bufOff = (uint32_t)(((st & 1) ? 0 : AS_FLOATS) * 4);
            #pragma unroll
            for (int i = 0; i < 4; i++) {
                const int o0 = lc[i] * 260 + gc0;
                st_cluster_b64(peerU + bufOff + (uint32_t)o0 * 4, packf2(h[i][0], h[i][1]));
                *(float2*)&An[o0] = make_float2(h[i][0], h[i][1]);
            }
        }

        // global output
        #pragma unroll
        for (int i = 0; i < 4; i++) {
            float* op = P.out + b * P.o_sb + st * P.o_sstep + jc[i] * P.o_sj + gc0;
            *(float2*)op = make_float2(h[i][0], h[i][1]);
        }

        CLUSTER_SYNC();   // orders state stores (incl. DSMEM) before next step
    }
}

// ---------------------------------------------------------------------------
// Host orchestration: 3 x (prepass GEMMs + 1 cluster recurrence) = 9 launches.
// ---------------------------------------------------------------------------
extern "C" void kernel_launch(void* const* d_in, const int* in_sizes, int n_in,
                              void* d_out, int out_size)
{
    const float* src   = (const float*)d_in[0];
    const float* trg   = (const float*)d_in[1];
    const float* Wx_ih = (const float*)d_in[2];
    const float* Wx_hh = (const float*)d_in[3];
    const float* bx_ih = (const float*)d_in[4];
    const float* bx_hh = (const float*)d_in[5];
    const float* Wy_ih = (const float*)d_in[6];
    const float* Wy_hh = (const float*)d_in[7];
    const float* by_ih = (const float*)d_in[8];
    const float* by_hh = (const float*)d_in[9];
    float* out = (float*)d_out;

    float *pre_x, *pre_y, *hx, *hy, *psx, *psy;
    cudaGetSymbolAddress((void**)&pre_x, g_pre_x);
    cudaGetSymbolAddress((void**)&pre_y, g_pre_y);
    cudaGetSymbolAddress((void**)&hx,    g_hx);
    cudaGetSymbolAddress((void**)&hy,    g_hy);
    cudaGetSymbolAddress((void**)&psx,   g_psx);
    cudaGetSymbolAddress((void**)&psy,   g_psy);

    cudaFuncSetAttribute(recur2,
                         cudaFuncAttributeMaxDynamicSharedMemorySize, RECUR_SMEM);
    cudaFuncSetAttribute(gemm128_bias,
                         cudaFuncAttributeMaxDynamicSharedMemorySize, GEMM_SMEM);

    for (int d = 0; d < 3; d++) {
        // ---- prepass: input projection + fused biases ----
        if (d == 0) {
            gemm128_bias<<<dim3(B * S / 128, 2), 256, GEMM_SMEM>>>(
                src, Wx_ih, bx_ih, bx_hh, psx);
            gemm128_bias<<<dim3(B * T / 128, 2), 256, GEMM_SMEM>>>(
                trg, Wy_ih, by_ih, by_hh, psy);
        } else {
            gemm128_bias<<<dim3(B * S * T / 128, 2), 256, GEMM_SMEM>>>(
                hx, Wx_ih + (size_t)d * H * H, bx_ih + d * H, bx_hh + d * H, pre_x);
            gemm128_bias<<<dim3(B * S * T / 128, 2), 256, GEMM_SMEM>>>(
                hy, Wy_ih + (size_t)d * H * H, by_ih + d * H, by_hh + d * H, pre_y);
        }

        const long OS = (d == 2) ? 2 * H : H;
        float* Ox = (d == 2) ? out     : hx;
        float* Oy = (d == 2) ? out + H : hy;

        RP X, Y;
        X.W = Wx_hh + (size_t)d * H * H;  X.diag = 1;
        X.out = Ox; X.o_sb = (long)S * T * OS; X.o_sstep = (long)T * OS; X.o_sj = OS;
        if (d == 0) { X.pre = psx;   X.p_sb = (long)S * H;     X.p_sstep = H;           X.p_sj = 0; }
        else        { X.pre = pre_x; X.p_sb = (long)S * T * H; X.p_sstep = (long)T * H; X.p_sj = H; }

        Y.W = Wy_hh + (size_t)d * H * H;  Y.diag = 0;
        Y.out = Oy; Y.o_sb = (long)S * T * OS; Y.o_sstep = OS; Y.o_sj = (long)T * OS;
        if (d == 0) { Y.pre = psy;   Y.p_sb = (long)T * H;     Y.p_sstep = H; Y.p_sj = 0; }
        else        { Y.pre = pre_y; Y.p_sb = (long)S * T * H; Y.p_sstep = H; Y.p_sj = (long)T * H; }

        recur2<<<dim3(2, 64), 256, RECUR_SMEM>>>(X, Y);
    }
}

// round 10
// speedup vs baseline: 1.0483x; 1.0483x over previous
#include <cuda_runtime.h>
#include <math.h>
#include <stdint.h>

constexpr int H = 256;
constexpr int B = 4;
constexpr int S = 128;
constexpr int T = 128;

typedef unsigned long long ull;

// Scratch (device globals — no allocation allowed)
__device__ float g_pre_x[(size_t)B * S * T * H];
__device__ float g_pre_y[(size_t)B * S * T * H];
__device__ float g_hx  [(size_t)B * S * T * H];
__device__ float g_hy  [(size_t)B * S * T * H];
__device__ float g_psx [(size_t)B * S * H];
__device__ float g_psy [(size_t)B * T * H];

// ---------------- packed f32x2 + PTX helpers ----------------
__device__ __forceinline__ void ffma2(ull& d, ull a, ull b) {
    asm("fma.rn.f32x2 %0, %1, %2, %0;" : "+l"(d) : "l"(a), "l"(b));
}
__device__ __forceinline__ float hsum2(ull v) {
    float lo, hi;
    asm("mov.b64 {%0, %1}, %2;" : "=f"(lo), "=f"(hi) : "l"(v));
    return lo + hi;
}
__device__ __forceinline__ ull packf2(float a, float b) {
    ull r; asm("mov.b64 %0, {%1, %2};" : "=l"(r) : "f"(a), "f"(b)); return r;
}
__device__ __forceinline__ uint32_t smem_u32(const void* p) {
    uint32_t a;
    asm("{ .reg .u64 t; cvta.to.shared.u64 t, %1; cvt.u32.u64 %0, t; }" : "=r"(a) : "l"(p));
    return a;
}
__device__ __forceinline__ uint32_t mapa_u32(uint32_t addr, uint32_t rank) {
    uint32_t r;
    asm("mapa.shared::cluster.u32 %0, %1, %2;" : "=r"(r) : "r"(addr), "r"(rank));
    return r;
}
__device__ __forceinline__ void st_cluster_b64(uint32_t addr, ull v) {
    asm volatile("st.shared::cluster.b64 [%0], %1;" :: "r"(addr), "l"(v) : "memory");
}
#define CLUSTER_ARRIVE() asm volatile("barrier.cluster.arrive.aligned;" ::: "memory")
#define CLUSTER_WAIT()   asm volatile("barrier.cluster.wait.aligned;" ::: "memory")

// Accurate tanh regardless of --use_fast_math
__device__ __forceinline__ float my_tanh(float x) {
    float ax = fabsf(x);
    float e  = expf(-2.0f * ax);
    float t  = (1.0f - e) / (1.0f + e);
    return x < 0.0f ? -t : t;
}

// ---------------------------------------------------------------------------
// Prepass GEMM (k-split f32x2): C[m,n] = sum_k A[m,k]*W[n,k] + b1[n] + b2[n]
// N=K=256. BM=128, BN=64, BK=32, 256 thr, 8m x 4n per thread.  (R8 shape —
// measured best; FFMA2 rt=3 RF-bank ceiling makes larger panels useless.)
// ---------------------------------------------------------------------------
__global__ void __launch_bounds__(256, 1) gemm256_bias(
    const float* __restrict__ A, const float* __restrict__ W,
    const float* __restrict__ b1, const float* __restrict__ b2,
    float* __restrict__ C)
{
    __shared__ float As[128 * 36];   // [m][k], +4 pad
    __shared__ float Bs[64 * 36];    // [n][k]

    const int m0  = blockIdx.x << 7;
    const int n0  = blockIdx.y << 6;
    const int tid = threadIdx.x;
    const int tx  = tid & 15;        // n lanes (cols tx + 16j)
    const int ty  = tid >> 4;        // m lanes (rows ty + 16i)
    const int lr0 = tid >> 3;        // 0..31 base load row
    const int lk  = (tid & 7) << 2;  // 0,4,...,28

    const float* Ap = A + (size_t)(m0 + lr0) * H + lk;
    const float* Wp = W + (size_t)(n0 + lr0) * H + lk;

    float4 pa[4], pb[2];
    #pragma unroll
    for (int s = 0; s < 4; s++) pa[s] = *(const float4*)(Ap + (size_t)(s << 5) * H);
    #pragma unroll
    for (int s = 0; s < 2; s++) pb[s] = *(const float4*)(Wp + (size_t)(s << 5) * H);

    ull acc[8][4] = {};

    for (int c = 0; c < 8; c++) {
        #pragma unroll
        for (int s = 0; s < 4; s++)
            *(float4*)&As[(lr0 + (s << 5)) * 36 + lk] = pa[s];
        #pragma unroll
        for (int s = 0; s < 2; s++)
            *(float4*)&Bs[(lr0 + (s << 5)) * 36 + lk] = pb[s];
        __syncthreads();

        if (c < 7) {
            int k = (c + 1) << 5;
            #pragma unroll
            for (int s = 0; s < 4; s++) pa[s] = *(const float4*)(Ap + (size_t)(s << 5) * H + k);
            #pragma unroll
            for (int s = 0; s < 2; s++) pb[s] = *(const float4*)(Wp + (size_t)(s << 5) * H + k);
        }

        #pragma unroll
        for (int kk = 0; kk < 32; kk += 4) {
            ulonglong2 Av[8], Wv[4];
            #pragma unroll
            for (int i = 0; i < 8; i++)
                Av[i] = *(const ulonglong2*)&As[(ty + (i << 4)) * 36 + kk];
            #pragma unroll
            for (int j = 0; j < 4; j++)
                Wv[j] = *(const ulonglong2*)&Bs[(tx + (j << 4)) * 36 + kk];
            #pragma unroll
            for (int i = 0; i < 8; i++)
                #pragma unroll
                for (int j = 0; j < 4; j++)
                    ffma2(acc[i][j], Av[i].x, Wv[j].x);
            #pragma unroll
            for (int i = 0; i < 8; i++)
                #pragma unroll
                for (int j = 0; j < 4; j++)
                    ffma2(acc[i][j], Av[i].y, Wv[j].y);
        }
        __syncthreads();
    }

    float bv[4];
    #pragma unroll
    for (int j = 0; j < 4; j++) {
        int n = n0 + tx + (j << 4);
        bv[j] = b1[n] + b2[n];
    }
    #pragma unroll
    for (int i = 0; i < 8; i++) {
        float* Cp = C + (size_t)(m0 + ty + (i << 4)) * H + n0 + tx;
        #pragma unroll
        for (int j = 0; j < 4; j++)
            Cp[j << 4] = hsum2(acc[i][j]) + bv[j];
    }
}

// ---------------------------------------------------------------------------
// Recurrence: diagonal chains, cluster-2, W resident in SMEM, split-k-half
// pipelining: own-col k-half GEMM runs inside the arrive->wait window, hiding
// cluster barrier latency + peer DSMEM delivery + STG/LDG issue.
// grid (2, 64), cluster (2,1,1), 256 threads.
// Warp = 16 chains x 16 cols; lane = 4 chains x 2 cols.
// ---------------------------------------------------------------------------
struct RP {
    const float* W;                       // [256n][256k] row-major (this path+depth)
    const float* pre; long p_sb, p_sstep, p_sj;
    float*       out; long o_sb, o_sstep, o_sj;
    int diag;                             // 1 = x-path (j advances with step)
};

constexpr int W2_FLOATS = 128 * 260;          // [kpair][2*col(128)+pad]
constexpr int AS_FLOATS = 16 * 260;           // [chain][k(256)+pad]
constexpr int RECUR_SMEM = (W2_FLOATS + 2 * AS_FLOATS) * 4;   // 166400 B

__global__ void __launch_bounds__(256, 1) __cluster_dims__(2, 1, 1)
recur2(RP X, RP Y)
{
    extern __shared__ float sm[];
    float* W2  = sm;                       // [128 kpairs][260]
    float* As0 = sm + W2_FLOATS;           // [16][260]
    float* As1 = As0 + AS_FLOATS;

    const int rank  = blockIdx.x;          // cluster rank 0/1
    const int clid  = blockIdx.y;
    const int path  = clid >> 5;
    const RP  P     = path ? Y : X;
    const int grp   = clid & 31;
    const int b     = grp >> 3;
    const int dbase = (grp & 7) << 4;

    const int tid  = threadIdx.x;
    const int w    = tid >> 5;             // warp 0..7 (16 cols each)
    const int lane = tid & 31;
    const int cg   = lane >> 3;            // chain group 0..3
    const int cls  = lane & 7;             // col lane 0..7
    const int c0L  = (w << 4) + (cls << 1);   // local cols c0L, c0L+1
    const int gc0  = (rank << 7) + c0L;

    int lc[4], dch[4];
    #pragma unroll
    for (int i = 0; i < 4; i++) { lc[i] = cg + (i << 2); dch[i] = dbase + lc[i]; }

    // ---- fill W2: W2[p][2c..2c+1] = {W[c][2p], W[c][2p+1]}, c = local col ----
    {
        const float* Wg = P.W + (size_t)(rank << 7) * H;
        for (int idx = tid; idx < 128 * 64; idx += 256) {
            int c = idx >> 6, kq = (idx & 63) << 2;
            float4 v = *(const float4*)&Wg[(size_t)c * H + kq];
            int p0 = kq >> 1;
            *(float2*)&W2[p0 * 260 + (c << 1)]       = make_float2(v.x, v.y);
            *(float2*)&W2[(p0 + 1) * 260 + (c << 1)] = make_float2(v.z, v.w);
        }
    }

    const uint32_t as0U  = smem_u32(As0);
    const uint32_t peerU = mapa_u32(as0U, rank ^ 1);
    const float* wBase = W2 + (c0L << 1);

    const int kOwn  = rank << 7;           // my cols' k-range (locally produced)
    const int kPeer = (rank ^ 1) << 7;     // peer-produced half

    // jc / pre prefetch for st = 0
    int jc[4];
    #pragma unroll
    for (int i = 0; i < 4; i++) jc[i] = dch[i];
    float2 pv[4];
    #pragma unroll
    for (int i = 0; i < 4; i++)
        pv[i] = *(const float2*)(P.pre + b * P.p_sb + jc[i] * P.p_sj + gc0);

    __syncthreads();   // W2 ready

    for (int st = 0; st < 128; st++) {
        ull acc[4][2] = {};

        if (st > 0) {
            const float* Ac = (st & 1) ? As1 : As0;   // state h(st-1)
            // ---- half 1: own-col k-range (already valid; runs inside the
            //      arrive->wait window, hiding barrier + peer DSMEM latency)
            #pragma unroll
            for (int half = 0; half < 2; half++) {
                const int k0 = half ? kPeer : kOwn;
                if (half) CLUSTER_WAIT();             // peer half now visible
                const float* a0 = Ac + lc[0] * 260 + k0;
                const float* a1 = Ac + lc[1] * 260 + k0;
                const float* a2 = Ac + lc[2] * 260 + k0;
                const float* a3 = Ac + lc[3] * 260 + k0;
                const float* wb = wBase + (k0 >> 1) * 260;
                #pragma unroll 8
                for (int k = 0; k < 128; k += 4) {
                    ulonglong2 A0 = *(const ulonglong2*)(a0 + k);
                    ulonglong2 A1 = *(const ulonglong2*)(a1 + k);
                    ulonglong2 A2 = *(const ulonglong2*)(a2 + k);
                    ulonglong2 A3 = *(const ulonglong2*)(a3 + k);
                    const float* wp = wb + (k >> 1) * 260;
                    ulonglong2 L0 = *(const ulonglong2*)(wp);          // kpair p
                    ulonglong2 L1 = *(const ulonglong2*)(wp + 260);    // kpair p+1
                    ffma2(acc[0][0], A0.x, L0.x); ffma2(acc[0][1], A0.x, L0.y);
                    ffma2(acc[1][0], A1.x, L0.x); ffma2(acc[1][1], A1.x, L0.y);
                    ffma2(acc[2][0], A2.x, L0.x); ffma2(acc[2][1], A2.x, L0.y);
                    ffma2(acc[3][0], A3.x, L0.x); ffma2(acc[3][1], A3.x, L0.y);
                    ffma2(acc[0][0], A0.y, L1.x); ffma2(acc[0][1], A0.y, L1.y);
                    ffma2(acc[1][0], A1.y, L1.x); ffma2(acc[1][1], A1.y, L1.y);
                    ffma2(acc[2][0], A2.y, L1.x); ffma2(acc[2][1], A2.y, L1.y);
                    ffma2(acc[3][0], A3.y, L1.x); ffma2(acc[3][1], A3.y, L1.y);
                }
            }
        }

        float h[4][2];
        #pragma unroll
        for (int i = 0; i < 4; i++) {
            h[i][0] = my_tanh(hsum2(acc[i][0]) + pv[i].x);
            h[i][1] = my_tanh(hsum2(acc[i][1]) + pv[i].y);
        }

        if (st < 127) {
            // publish state h(st): own SMEM + peer SMEM (DSMEM)
            float* An = (st & 1) ? As0 : As1;
            const uint32_t bufOff = (uint32_t)(((st & 1) ? 0 : AS_FLOATS) * 4);
            #pragma unroll
            for (int i = 0; i < 4; i++) {
                const int o0 = lc[i] * 260 + gc0;
                st_cluster_b64(peerU + bufOff + (uint32_t)o0 * 4, packf2(h[i][0], h[i][1]));
                *(float2*)&An[o0] = make_float2(h[i][0], h[i][1]);
            }
            __syncthreads();       // own-half visible CTA-wide before next reads
            CLUSTER_ARRIVE();      // releases DSMEM stores; matched by wait(st+1)
        }

        // global output (inside the arrive->wait window)
        #pragma unroll
        for (int i = 0; i < 4; i++) {
            float* op = P.out + b * P.o_sb + st * P.o_sstep + jc[i] * P.o_sj + gc0;
            *(float2*)op = make_float2(h[i][0], h[i][1]);
        }

        if (st < 127) {
            // advance jc and prefetch pre(st+1) — consumed after next GEMM
            if (P.diag) {
                #pragma unroll
                for (int i = 0; i < 4; i++) jc[i] = (jc[i] + 1) & 127;
            }
            #pragma unroll
            for (int i = 0; i < 4; i++)
                pv[i] = *(const float2*)(P.pre + b * P.p_sb + (st + 1) * P.p_sstep
                                         + jc[i] * P.p_sj + gc0);
        }
    }
}

// ---------------------------------------------------------------------------
// Host orchestration: 3 x (prepass GEMMs + 1 cluster recurrence) = 9 launches.
// ---------------------------------------------------------------------------
extern "C" void kernel_launch(void* const* d_in, const int* in_sizes, int n_in,
                              void* d_out, int out_size)
{
    const float* src   = (const float*)d_in[0];
    const float* trg   = (const float*)d_in[1];
    const float* Wx_ih = (const float*)d_in[2];
    const float* Wx_hh = (const float*)d_in[3];
    const float* bx_ih = (const float*)d_in[4];
    const float* bx_hh = (const float*)d_in[5];
    const float* Wy_ih = (const float*)d_in[6];
    const float* Wy_hh = (const float*)d_in[7];
    const float* by_ih = (const float*)d_in[8];
    const float* by_hh = (const float*)d_in[9];
    float* out = (float*)d_out;

    float *pre_x, *pre_y, *hx, *hy, *psx, *psy;
    cudaGetSymbolAddress((void**)&pre_x, g_pre_x);
    cudaGetSymbolAddress((void**)&pre_y, g_pre_y);
    cudaGetSymbolAddress((void**)&hx,    g_hx);
    cudaGetSymbolAddress((void**)&hy,    g_hy);
    cudaGetSymbolAddress((void**)&psx,   g_psx);
    cudaGetSymbolAddress((void**)&psy,   g_psy);

    cudaFuncSetAttribute(recur2,
                         cudaFuncAttributeMaxDynamicSharedMemorySize, RECUR_SMEM);

    for (int d = 0; d < 3; d++) {
        // ---- prepass: input projection + fused biases ----
        if (d == 0) {
            gemm256_bias<<<dim3(B * S / 128, H / 64), 256>>>(src, Wx_ih, bx_ih, bx_hh, psx);
            gemm256_bias<<<dim3(B * T / 128, H / 64), 256>>>(trg, Wy_ih, by_ih, by_hh, psy);
        } else {
            gemm256_bias<<<dim3(B * S * T / 128, H / 64), 256>>>(
                hx, Wx_ih + (size_t)d * H * H, bx_ih + d * H, bx_hh + d * H, pre_x);
            gemm256_bias<<<dim3(B * S * T / 128, H / 64), 256>>>(
                hy, Wy_ih + (size_t)d * H * H, by_ih + d * H, by_hh + d * H, pre_y);
        }

        const long OS = (d == 2) ? 2 * H : H;
        float* Ox = (d == 2) ? out     : hx;
        float* Oy = (d == 2) ? out + H : hy;

        RP X, Y;
        X.W = Wx_hh + (size_t)d * H * H;  X.diag = 1;
        X.out = Ox; X.o_sb = (long)S * T * OS; X.o_sstep = (long)T * OS; X.o_sj = OS;
        if (d == 0) { X.pre = psx;   X.p_sb = (long)S * H;     X.p_sstep = H;           X.p_sj = 0; }
        else        { X.pre = pre_x; X.p_sb = (long)S * T * H; X.p_sstep = (long)T * H; X.p_sj = H; }

        Y.W = Wy_hh + (size_t)d * H * H;  Y.diag = 0;
        Y.out = Oy; Y.o_sb = (long)S * T * OS; Y.o_sstep = OS; Y.o_sj = (long)T * OS;
        if (d == 0) { Y.pre = psy;   Y.p_sb = (long)T * H;     Y.p_sstep = H; Y.p_sj = 0; }
        else        { Y.pre = pre_y; Y.p_sb = (long)S * T * H; Y.p_sstep = H; Y.p_sj = (long)T * H; }

        recur2<<<dim3(2, 64), 256, RECUR_SMEM>>>(X, Y);
    }
}

// round 12
// speedup vs baseline: 1.1929x; 1.1380x over previous
#include <cuda_runtime.h>
#include <cuda_bf16.h>
#include <math.h>
#include <stdint.h>

constexpr int H = 256;
constexpr int B = 4;
constexpr int S = 128;
constexpr int T = 128;

typedef unsigned long long ull;

// Scratch (device globals — no allocation allowed)
__device__ float g_pre_x[(size_t)B * S * T * H];
__device__ float g_pre_y[(size_t)B * S * T * H];
__device__ float g_hx  [(size_t)B * S * T * H];
__device__ float g_hy  [(size_t)B * S * T * H];
__device__ float g_psx [(size_t)B * S * H];
__device__ float g_psy [(size_t)B * T * H];
// bf16 hi/lo splits of the 3-depth ih-weights (x and y paths)
__device__ __nv_bfloat16 g_wxh[3 * 256 * 256];
__device__ __nv_bfloat16 g_wxl[3 * 256 * 256];
__device__ __nv_bfloat16 g_wyh[3 * 256 * 256];
__device__ __nv_bfloat16 g_wyl[3 * 256 * 256];

// ---------------- packed f32x2 + PTX helpers ----------------
__device__ __forceinline__ void ffma2(ull& d, ull a, ull b) {
    asm("fma.rn.f32x2 %0, %1, %2, %0;" : "+l"(d) : "l"(a), "l"(b));
}
__device__ __forceinline__ float hsum2(ull v) {
    float lo, hi;
    asm("mov.b64 {%0, %1}, %2;" : "=f"(lo), "=f"(hi) : "l"(v));
    return lo + hi;
}
__device__ __forceinline__ ull packf2(float a, float b) {
    ull r; asm("mov.b64 %0, {%1, %2};" : "=l"(r) : "f"(a), "f"(b)); return r;
}
__device__ __forceinline__ uint32_t smem_u32(const void* p) {
    uint32_t a;
    asm("{ .reg .u64 t; cvta.to.shared.u64 t, %1; cvt.u32.u64 %0, t; }" : "=r"(a) : "l"(p));
    return a;
}
__device__ __forceinline__ uint32_t mapa_u32(uint32_t addr, uint32_t rank) {
    uint32_t r;
    asm("mapa.shared::cluster.u32 %0, %1, %2;" : "=r"(r) : "r"(addr), "r"(rank));
    return r;
}
__device__ __forceinline__ void st_cluster_b64(uint32_t addr, ull v) {
    asm volatile("st.shared::cluster.b64 [%0], %1;" :: "r"(addr), "l"(v) : "memory");
}
#define CLUSTER_ARRIVE() asm volatile("barrier.cluster.arrive.aligned;" ::: "memory")
#define CLUSTER_WAIT()   asm volatile("barrier.cluster.wait.aligned;" ::: "memory")

// Accurate tanh regardless of --use_fast_math
__device__ __forceinline__ float my_tanh(float x) {
    float ax = fabsf(x);
    float e  = expf(-2.0f * ax);
    float t  = (1.0f - e) / (1.0f + e);
    return x < 0.0f ? -t : t;
}

// bf16 MMA m16n8k16, fp32 accumulate (sm_80-era HMMA — compiles on compute_103)
__device__ __forceinline__ void mma_bf16(float* c, const uint32_t* a, const uint32_t* b) {
    asm volatile(
        "mma.sync.aligned.m16n8k16.row.col.f32.bf16.bf16.f32 "
        "{%0,%1,%2,%3}, {%4,%5,%6,%7}, {%8,%9}, {%0,%1,%2,%3};"
        : "+f"(c[0]), "+f"(c[1]), "+f"(c[2]), "+f"(c[3])
        : "r"(a[0]), "r"(a[1]), "r"(a[2]), "r"(a[3]), "r"(b[0]), "r"(b[1]));
}

// ---------------------------------------------------------------------------
// W split kernel: fp32 -> (hi, lo) bf16 pair.  lo = bf16(v - float(hi)).
// ---------------------------------------------------------------------------
__global__ void conv_w(const float* __restrict__ W,
                       __nv_bfloat16* __restrict__ hi,
                       __nv_bfloat16* __restrict__ lo, int n)
{
    int i = blockIdx.x * 256 + threadIdx.x;
    if (i < n) {
        float v = W[i];
        __nv_bfloat16 h = __float2bfloat16_rn(v);
        hi[i] = h;
        lo[i] = __float2bfloat16_rn(v - __bfloat162float(h));
    }
}

// ---------------------------------------------------------------------------
// HMMA prepass: C[m,n] = sum_k A[m,k]*W[n,k] + b1[n] + b2[n]
// fp32 via bf16x3: acc += Ah*Wh + Ah*Wl + Al*Wh  (fp32 HMMA accumulators).
// BM=BN=128, BK=32, K=256, 256 thr (8 warps, 2x4), warp tile m64 x n32.
// W[n][k] row-major == col-major B fragment: every frag load is one LDS.32,
// conflict-free at row stride 40 bf16 (bank = 20g+t mod 32, all distinct).
// ---------------------------------------------------------------------------
constexpr int PSTR = 40;   // smem row stride in bf16

__global__ void __launch_bounds__(256, 1) hmma_prepass(
    const float* __restrict__ A,
    const __nv_bfloat16* __restrict__ Whi, const __nv_bfloat16* __restrict__ Wlo,
    const float* __restrict__ b1, const float* __restrict__ b2,
    float* __restrict__ C)
{
    __shared__ __nv_bfloat16 Ah[128 * PSTR], Al[128 * PSTR];
    __shared__ __nv_bfloat16 Wh[128 * PSTR], Wl[128 * PSTR];
    __shared__ float bs[128];

    const int m0  = blockIdx.x << 7;
    const int n0  = blockIdx.y << 7;
    const int tid = threadIdx.x;
    const int wid = tid >> 5;
    const int lane = tid & 31;
    const int gid = lane >> 2;       // group 0..7
    const int tg  = lane & 3;        // thread-in-group
    const int wm  = wid >> 2;        // 0..1
    const int wn  = wid & 3;         // 0..3

    if (tid < 128) bs[tid] = b1[n0 + tid] + b2[n0 + tid];

    // staging map: row = tid>>1 (0..127), half = tid&1 (16 cols each)
    const int srow = tid >> 1;
    const int shalf = (tid & 1) << 4;
    const float* Ag = A + (size_t)(m0 + srow) * H + shalf;
    const __nv_bfloat16* WhG = Whi + (size_t)(n0 + srow) * H + shalf;
    const __nv_bfloat16* WlG = Wlo + (size_t)(n0 + srow) * H + shalf;

    float4 pa[4];
    uint4  pwh[2], pwl[2];
    #pragma unroll
    for (int q = 0; q < 4; q++) pa[q] = *(const float4*)(Ag + q * 4);
    #pragma unroll
    for (int q = 0; q < 2; q++) {
        pwh[q] = *(const uint4*)(WhG + q * 8);
        pwl[q] = *(const uint4*)(WlG + q * 8);
    }

    float acc[4][4][4] = {};

    for (int kc = 0; kc < 8; kc++) {
        // ---- STS staged chunk (convert A to hi/lo) ----
        #pragma unroll
        for (int q = 0; q < 4; q++) {
            float4 v = pa[q];
            __nv_bfloat16 h0 = __float2bfloat16_rn(v.x);
            __nv_bfloat16 h1 = __float2bfloat16_rn(v.y);
            __nv_bfloat16 h2 = __float2bfloat16_rn(v.z);
            __nv_bfloat16 h3 = __float2bfloat16_rn(v.w);
            uint2 uh, ul;
            uh.x = ((uint32_t)__bfloat16_as_ushort(h1) << 16) | __bfloat16_as_ushort(h0);
            uh.y = ((uint32_t)__bfloat16_as_ushort(h3) << 16) | __bfloat16_as_ushort(h2);
            __nv_bfloat16 l0 = __float2bfloat16_rn(v.x - __bfloat162float(h0));
            __nv_bfloat16 l1 = __float2bfloat16_rn(v.y - __bfloat162float(h1));
            __nv_bfloat16 l2 = __float2bfloat16_rn(v.z - __bfloat162float(h2));
            __nv_bfloat16 l3 = __float2bfloat16_rn(v.w - __bfloat162float(h3));
            ul.x = ((uint32_t)__bfloat16_as_ushort(l1) << 16) | __bfloat16_as_ushort(l0);
            ul.y = ((uint32_t)__bfloat16_as_ushort(l3) << 16) | __bfloat16_as_ushort(l2);
            *(uint2*)&Ah[srow * PSTR + shalf + q * 4] = uh;
            *(uint2*)&Al[srow * PSTR + shalf + q * 4] = ul;
        }
        #pragma unroll
        for (int q = 0; q < 2; q++) {
            *(uint4*)&Wh[srow * PSTR + shalf + q * 8] = pwh[q];
            *(uint4*)&Wl[srow * PSTR + shalf + q * 8] = pwl[q];
        }
        __syncthreads();

        if (kc < 7) {
            const int kb = (kc + 1) << 5;
            #pragma unroll
            for (int q = 0; q < 4; q++) pa[q] = *(const float4*)(Ag + kb + q * 4);
            #pragma unroll
            for (int q = 0; q < 2; q++) {
                pwh[q] = *(const uint4*)(WhG + kb + q * 8);
                pwl[q] = *(const uint4*)(WlG + kb + q * 8);
            }
        }

        // ---- MMA over BK=32 (2 k16 steps) ----
        #pragma unroll
        for (int ks = 0; ks < 32; ks += 16) {
            uint32_t ah[4][4], al[4][4], wh[4][2], wl[4][2];
            #pragma unroll
            for (int fm = 0; fm < 4; fm++) {
                const int r0 = ((wm << 6) + (fm << 4) + gid) * PSTR + ks + (tg << 1);
                ah[fm][0] = *(const uint32_t*)&Ah[r0];
                ah[fm][1] = *(const uint32_t*)&Ah[r0 + 8 * PSTR];
                ah[fm][2] = *(const uint32_t*)&Ah[r0 + 8];
                ah[fm][3] = *(const uint32_t*)&Ah[r0 + 8 * PSTR + 8];
                al[fm][0] = *(const uint32_t*)&Al[r0];
                al[fm][1] = *(const uint32_t*)&Al[r0 + 8 * PSTR];
                al[fm][2] = *(const uint32_t*)&Al[r0 + 8];
                al[fm][3] = *(const uint32_t*)&Al[r0 + 8 * PSTR + 8];
            }
            #pragma unroll
            for (int fn = 0; fn < 4; fn++) {
                const int nb = ((wn << 5) + (fn << 3) + gid) * PSTR + ks + (tg << 1);
                wh[fn][0] = *(const uint32_t*)&Wh[nb];
                wh[fn][1] = *(const uint32_t*)&Wh[nb + 8];
                wl[fn][0] = *(const uint32_t*)&Wl[nb];
                wl[fn][1] = *(const uint32_t*)&Wl[nb + 8];
            }
            #pragma unroll
            for (int fm = 0; fm < 4; fm++)
                #pragma unroll
                for (int fn = 0; fn < 4; fn++) {
                    mma_bf16(acc[fm][fn], ah[fm], wh[fn]);
                    mma_bf16(acc[fm][fn], ah[fm], wl[fn]);
                    mma_bf16(acc[fm][fn], al[fm], wh[fn]);
                }
        }
        __syncthreads();
    }

    // ---- epilogue: acc + bias -> C ----
    #pragma unroll
    for (int fm = 0; fm < 4; fm++) {
        const int row = m0 + (wm << 6) + (fm << 4) + gid;
        #pragma unroll
        for (int fn = 0; fn < 4; fn++) {
            const int colL = (wn << 5) + (fn << 3) + (tg << 1);
            const float2 bv = *(const float2*)&bs[colL];
            const float* c = acc[fm][fn];
            float* Cp = C + (size_t)row * H + n0 + colL;
            *(float2*)Cp = make_float2(c[0] + bv.x, c[1] + bv.y);
            *(float2*)(Cp + 8 * H) = make_float2(c[2] + bv.x, c[3] + bv.y);
        }
    }
}

// ---------------------------------------------------------------------------
// Recurrence: UNCHANGED from R10 (passing).  Diagonal chains, cluster-2,
// W resident in SMEM, split-k-half pipelining across the arrive->wait window.
// ---------------------------------------------------------------------------
struct RP {
    const float* W;
    const float* pre; long p_sb, p_sstep, p_sj;
    float*       out; long o_sb, o_sstep, o_sj;
    int diag;
};

constexpr int W2_FLOATS = 128 * 260;
constexpr int AS_FLOATS = 16 * 260;
constexpr int RECUR_SMEM = (W2_FLOATS + 2 * AS_FLOATS) * 4;   // 166400 B

__global__ void __launch_bounds__(256, 1) __cluster_dims__(2, 1, 1)
recur2(RP X, RP Y)
{
    extern __shared__ float sm[];
    float* W2  = sm;
    float* As0 = sm + W2_FLOATS;
    float* As1 = As0 + AS_FLOATS;

    const int rank  = blockIdx.x;
    const int clid  = blockIdx.y;
    const int path  = clid >> 5;
    const RP  P     = path ? Y : X;
    const int grp   = clid & 31;
    const int b     = grp >> 3;
    const int dbase = (grp & 7) << 4;

    const int tid  = threadIdx.x;
    const int w    = tid >> 5;
    const int lane = tid & 31;
    const int cg   = lane >> 3;
    const int cls  = lane & 7;
    const int c0L  = (w << 4) + (cls << 1);
    const int gc0  = (rank << 7) + c0L;

    int lc[4], dch[4];
    #pragma unroll
    for (int i = 0; i < 4; i++) { lc[i] = cg + (i << 2); dch[i] = dbase + lc[i]; }

    {
        const float* Wg = P.W + (size_t)(rank << 7) * H;
        for (int idx = tid; idx < 128 * 64; idx += 256) {
            int c = idx >> 6, kq = (idx & 63) << 2;
            float4 v = *(const float4*)&Wg[(size_t)c * H + kq];
            int p0 = kq >> 1;
            *(float2*)&W2[p0 * 260 + (c << 1)]       = make_float2(v.x, v.y);
            *(float2*)&W2[(p0 + 1) * 260 + (c << 1)] = make_float2(v.z, v.w);
        }
    }

    const uint32_t as0U  = smem_u32(As0);
    const uint32_t peerU = mapa_u32(as0U, rank ^ 1);
    const float* wBase = W2 + (c0L << 1);

    const int kOwn  = rank << 7;
    const int kPeer = (rank ^ 1) << 7;

    int jc[4];
    #pragma unroll
    for (int i = 0; i < 4; i++) jc[i] = dch[i];
    float2 pv[4];
    #pragma unroll
    for (int i = 0; i < 4; i++)
        pv[i] = *(const float2*)(P.pre + b * P.p_sb + jc[i] * P.p_sj + gc0);

    __syncthreads();

    for (int st = 0; st < 128; st++) {
        ull acc[4][2] = {};

        if (st > 0) {
            const float* Ac = (st & 1) ? As1 : As0;
            #pragma unroll
            for (int half = 0; half < 2; half++) {
                const int k0 = half ? kPeer : kOwn;
                if (half) CLUSTER_WAIT();
                const float* a0 = Ac + lc[0] * 260 + k0;
                const float* a1 = Ac + lc[1] * 260 + k0;
                const float* a2 = Ac + lc[2] * 260 + k0;
                const float* a3 = Ac + lc[3] * 260 + k0;
                const float* wb = wBase + (k0 >> 1) * 260;
                #pragma unroll 8
                for (int k = 0; k < 128; k += 4) {
                    ulonglong2 A0 = *(const ulonglong2*)(a0 + k);
                    ulonglong2 A1 = *(const ulonglong2*)(a1 + k);
                    ulonglong2 A2 = *(const ulonglong2*)(a2 + k);
                    ulonglong2 A3 = *(const ulonglong2*)(a3 + k);
                    const float* wp = wb + (k >> 1) * 260;
                    ulonglong2 L0 = *(const ulonglong2*)(wp);
                    ulonglong2 L1 = *(const ulonglong2*)(wp + 260);
                    ffma2(acc[0][0], A0.x, L0.x); ffma2(acc[0][1], A0.x, L0.y);
                    ffma2(acc[1][0], A1.x, L0.x); ffma2(acc[1][1], A1.x, L0.y);
                    ffma2(acc[2][0], A2.x, L0.x); ffma2(acc[2][1], A2.x, L0.y);
                    ffma2(acc[3][0], A3.x, L0.x); ffma2(acc[3][1], A3.x, L0.y);
                    ffma2(acc[0][0], A0.y, L1.x); ffma2(acc[0][1], A0.y, L1.y);
                    ffma2(acc[1][0], A1.y, L1.x); ffma2(acc[1][1], A1.y, L1.y);
                    ffma2(acc[2][0], A2.y, L1.x); ffma2(acc[2][1], A2.y, L1.y);
                    ffma2(acc[3][0], A3.y, L1.x); ffma2(acc[3][1], A3.y, L1.y);
                }
            }
        }

        float h[4][2];
        #pragma unroll
        for (int i = 0; i < 4; i++) {
            h[i][0] = my_tanh(hsum2(acc[i][0]) + pv[i].x);
            h[i][1] = my_tanh(hsum2(acc[i][1]) + pv[i].y);
        }

        if (st < 127) {
            float* An = (st & 1) ? As0 : As1;
            const uint32_t bufOff = (uint32_t)(((st & 1) ? 0 : AS_FLOATS) * 4);
            #pragma unroll
            for (int i = 0; i < 4; i++) {
                const int o0 = lc[i] * 260 + gc0;
                st_cluster_b64(peerU + bufOff + (uint32_t)o0 * 4, packf2(h[i][0], h[i][1]));
                *(float2*)&An[o0] = make_float2(h[i][0], h[i][1]);
            }
            __syncthreads();
            CLUSTER_ARRIVE();
        }

        #pragma unroll
        for (int i = 0; i < 4; i++) {
            float* op = P.out + b * P.o_sb + st * P.o_sstep + jc[i] * P.o_sj + gc0;
            *(float2*)op = make_float2(h[i][0], h[i][1]);
        }

        if (st < 127) {
            if (P.diag) {
                #pragma unroll
                for (int i = 0; i < 4; i++) jc[i] = (jc[i] + 1) & 127;
            }
            #pragma unroll
            for (int i = 0; i < 4; i++)
                pv[i] = *(const float2*)(P.pre + b * P.p_sb + (st + 1) * P.p_sstep
                                         + jc[i] * P.p_sj + gc0);
        }
    }
}

// ---------------------------------------------------------------------------
// Host orchestration: 2 W-split + 3 x (2 prepass + 1 recurrence) launches.
// ---------------------------------------------------------------------------
extern "C" void kernel_launch(void* const* d_in, const int* in_sizes, int n_in,
                              void* d_out, int out_size)
{
    const float* src   = (const float*)d_in[0];
    const float* trg   = (const float*)d_in[1];
    const float* Wx_ih = (const float*)d_in[2];
    const float* Wx_hh = (const float*)d_in[3];
    const float* bx_ih = (const float*)d_in[4];
    const float* bx_hh = (const float*)d_in[5];
    const float* Wy_ih = (const float*)d_in[6];
    const float* Wy_hh = (const float*)d_in[7];
    const float* by_ih = (const float*)d_in[8];
    const float* by_hh = (const float*)d_in[9];
    float* out = (float*)d_out;

    float *pre_x, *pre_y, *hx, *hy, *psx, *psy;
    __nv_bfloat16 *wxh, *wxl, *wyh, *wyl;
    cudaGetSymbolAddress((void**)&pre_x, g_pre_x);
    cudaGetSymbolAddress((void**)&pre_y, g_pre_y);
    cudaGetSymbolAddress((void**)&hx,    g_hx);
    cudaGetSymbolAddress((void**)&hy,    g_hy);
    cudaGetSymbolAddress((void**)&psx,   g_psx);
    cudaGetSymbolAddress((void**)&psy,   g_psy);
    cudaGetSymbolAddress((void**)&wxh,   g_wxh);
    cudaGetSymbolAddress((void**)&wxl,   g_wxl);
    cudaGetSymbolAddress((void**)&wyh,   g_wyh);
    cudaGetSymbolAddress((void**)&wyl,   g_wyl);

    cudaFuncSetAttribute(recur2,
                         cudaFuncAttributeMaxDynamicSharedMemorySize, RECUR_SMEM);

    const int nW = 3 * 256 * 256;
    conv_w<<<(nW + 255) / 256, 256>>>(Wx_ih, wxh, wxl, nW);
    conv_w<<<(nW + 255) / 256, 256>>>(Wy_ih, wyh, wyl, nW);

    for (int d = 0; d < 3; d++) {
        const int woff = d * 256 * 256;
        if (d == 0) {
            hmma_prepass<<<dim3(B * S / 128, 2), 256>>>(
                src, wxh + woff, wxl + woff, bx_ih, bx_hh, psx);
            hmma_prepass<<<dim3(B * T / 128, 2), 256>>>(
                trg, wyh + woff, wyl + woff, by_ih, by_hh, psy);
        } else {
            hmma_prepass<<<dim3(B * S * T / 128, 2), 256>>>(
                hx, wxh + woff, wxl + woff, bx_ih + d * H, bx_hh + d * H, pre_x);
            hmma_prepass<<<dim3(B * S * T / 128, 2), 256>>>(
                hy, wyh + woff, wyl + woff, by_ih + d * H, by_hh + d * H, pre_y);
        }

        const long OS = (d == 2) ? 2 * H : H;
        float* Ox = (d == 2) ? out     : hx;
        float* Oy = (d == 2) ? out + H : hy;

        RP X, Y;
        X.W = Wx_hh + (size_t)d * H * H;  X.diag = 1;
        X.out = Ox; X.o_sb = (long)S * T * OS; X.o_sstep = (long)T * OS; X.o_sj = OS;
        if (d == 0) { X.pre = psx;   X.p_sb = (long)S * H;     X.p_sstep = H;           X.p_sj = 0; }
        else        { X.pre = pre_x; X.p_sb = (long)S * T * H; X.p_sstep = (long)T * H; X.p_sj = H; }

        Y.W = Wy_hh + (size_t)d * H * H;  Y.diag = 0;
        Y.out = Oy; Y.o_sb = (long)S * T * OS; Y.o_sstep = OS; Y.o_sj = (long)T * OS;
        if (d == 0) { Y.pre = psy;   Y.p_sb = (long)T * H;     Y.p_sstep = H; Y.p_sj = 0; }
        else        { Y.pre = pre_y; Y.p_sb = (long)S * T * H; Y.p_sstep = H; Y.p_sj = (long)T * H; }

        recur2<<<dim3(2, 64), 256, RECUR_SMEM>>>(X, Y);
    }
}

// round 13
// speedup vs baseline: 1.7438x; 1.4618x over previous
#include <cuda_runtime.h>
#include <cuda_bf16.h>
#include <math.h>
#include <stdint.h>

constexpr int H = 256;
constexpr int B = 4;
constexpr int S = 128;
constexpr int T = 128;

typedef unsigned long long ull;

// Scratch (device globals — no allocation allowed)
__device__ float g_pre_x[(size_t)B * S * T * H];
__device__ float g_pre_y[(size_t)B * S * T * H];
__device__ float g_hx  [(size_t)B * S * T * H];
__device__ float g_hy  [(size_t)B * S * T * H];
__device__ float g_psx [(size_t)B * S * H];
__device__ float g_psy [(size_t)B * T * H];
// bf16 hi/lo splits of the 3-depth ih-weights (x and y paths)
__device__ __nv_bfloat16 g_wxh[3 * 256 * 256];
__device__ __nv_bfloat16 g_wxl[3 * 256 * 256];
__device__ __nv_bfloat16 g_wyh[3 * 256 * 256];
__device__ __nv_bfloat16 g_wyl[3 * 256 * 256];

// ---------------- PTX helpers ----------------
__device__ __forceinline__ uint32_t smem_u32(const void* p) {
    uint32_t a;
    asm("{ .reg .u64 t; cvta.to.shared.u64 t, %1; cvt.u32.u64 %0, t; }" : "=r"(a) : "l"(p));
    return a;
}
__device__ __forceinline__ uint32_t mapa_u32(uint32_t addr, uint32_t rank) {
    uint32_t r;
    asm("mapa.shared::cluster.u32 %0, %1, %2;" : "=r"(r) : "r"(addr), "r"(rank));
    return r;
}
__device__ __forceinline__ void st_cluster_b32(uint32_t addr, uint32_t v) {
    asm volatile("st.shared::cluster.b32 [%0], %1;" :: "r"(addr), "r"(v) : "memory");
}
#define CLUSTER_ARRIVE() asm volatile("barrier.cluster.arrive.aligned;" ::: "memory")
#define CLUSTER_WAIT()   asm volatile("barrier.cluster.wait.aligned;" ::: "memory")

// Accurate tanh regardless of --use_fast_math
__device__ __forceinline__ float my_tanh(float x) {
    float ax = fabsf(x);
    float e  = expf(-2.0f * ax);
    float t  = (1.0f - e) / (1.0f + e);
    return x < 0.0f ? -t : t;
}

// bf16 MMA m16n8k16, fp32 accumulate (sm_80-era HMMA — compiles on compute_103)
__device__ __forceinline__ void mma_bf16(float* c, const uint32_t* a, const uint32_t* b) {
    asm volatile(
        "mma.sync.aligned.m16n8k16.row.col.f32.bf16.bf16.f32 "
        "{%0,%1,%2,%3}, {%4,%5,%6,%7}, {%8,%9}, {%0,%1,%2,%3};"
        : "+f"(c[0]), "+f"(c[1]), "+f"(c[2]), "+f"(c[3])
        : "r"(a[0]), "r"(a[1]), "r"(a[2]), "r"(a[3]), "r"(b[0]), "r"(b[1]));
}

__device__ __forceinline__ uint32_t pack_bf16x2(float a, float b) {
    return ((uint32_t)__bfloat16_as_ushort(__float2bfloat16_rn(b)) << 16)
         | __bfloat16_as_ushort(__float2bfloat16_rn(a));
}

// ---------------------------------------------------------------------------
// W split kernel: fp32 -> (hi, lo) bf16 pair.  lo = bf16(v - float(hi)).
// ---------------------------------------------------------------------------
__global__ void conv_w(const float* __restrict__ W,
                       __nv_bfloat16* __restrict__ hi,
                       __nv_bfloat16* __restrict__ lo, int n)
{
    int i = blockIdx.x * 256 + threadIdx.x;
    if (i < n) {
        float v = W[i];
        __nv_bfloat16 h = __float2bfloat16_rn(v);
        hi[i] = h;
        lo[i] = __float2bfloat16_rn(v - __bfloat162float(h));
    }
}

// ---------------------------------------------------------------------------
// HMMA prepass (UNCHANGED from R12, passing): C = A W^T + b1 + b2, bf16x3.
// ---------------------------------------------------------------------------
constexpr int PSTR = 40;   // smem row stride in bf16

__global__ void __launch_bounds__(256, 1) hmma_prepass(
    const float* __restrict__ A,
    const __nv_bfloat16* __restrict__ Whi, const __nv_bfloat16* __restrict__ Wlo,
    const float* __restrict__ b1, const float* __restrict__ b2,
    float* __restrict__ C)
{
    __shared__ __nv_bfloat16 Ah[128 * PSTR], Al[128 * PSTR];
    __shared__ __nv_bfloat16 Wh[128 * PSTR], Wl[128 * PSTR];
    __shared__ float bs[128];

    const int m0  = blockIdx.x << 7;
    const int n0  = blockIdx.y << 7;
    const int tid = threadIdx.x;
    const int wid = tid >> 5;
    const int lane = tid & 31;
    const int gid = lane >> 2;
    const int tg  = lane & 3;
    const int wm  = wid >> 2;
    const int wn  = wid & 3;

    if (tid < 128) bs[tid] = b1[n0 + tid] + b2[n0 + tid];

    const int srow = tid >> 1;
    const int shalf = (tid & 1) << 4;
    const float* Ag = A + (size_t)(m0 + srow) * H + shalf;
    const __nv_bfloat16* WhG = Whi + (size_t)(n0 + srow) * H + shalf;
    const __nv_bfloat16* WlG = Wlo + (size_t)(n0 + srow) * H + shalf;

    float4 pa[4];
    uint4  pwh[2], pwl[2];
    #pragma unroll
    for (int q = 0; q < 4; q++) pa[q] = *(const float4*)(Ag + q * 4);
    #pragma unroll
    for (int q = 0; q < 2; q++) {
        pwh[q] = *(const uint4*)(WhG + q * 8);
        pwl[q] = *(const uint4*)(WlG + q * 8);
    }

    float acc[4][4][4] = {};

    for (int kc = 0; kc < 8; kc++) {
        #pragma unroll
        for (int q = 0; q < 4; q++) {
            float4 v = pa[q];
            __nv_bfloat16 h0 = __float2bfloat16_rn(v.x);
            __nv_bfloat16 h1 = __float2bfloat16_rn(v.y);
            __nv_bfloat16 h2 = __float2bfloat16_rn(v.z);
            __nv_bfloat16 h3 = __float2bfloat16_rn(v.w);
            uint2 uh, ul;
            uh.x = ((uint32_t)__bfloat16_as_ushort(h1) << 16) | __bfloat16_as_ushort(h0);
            uh.y = ((uint32_t)__bfloat16_as_ushort(h3) << 16) | __bfloat16_as_ushort(h2);
            __nv_bfloat16 l0 = __float2bfloat16_rn(v.x - __bfloat162float(h0));
            __nv_bfloat16 l1 = __float2bfloat16_rn(v.y - __bfloat162float(h1));
            __nv_bfloat16 l2 = __float2bfloat16_rn(v.z - __bfloat162float(h2));
            __nv_bfloat16 l3 = __float2bfloat16_rn(v.w - __bfloat162float(h3));
            ul.x = ((uint32_t)__bfloat16_as_ushort(l1) << 16) | __bfloat16_as_ushort(l0);
            ul.y = ((uint32_t)__bfloat16_as_ushort(l3) << 16) | __bfloat16_as_ushort(l2);
            *(uint2*)&Ah[srow * PSTR + shalf + q * 4] = uh;
            *(uint2*)&Al[srow * PSTR + shalf + q * 4] = ul;
        }
        #pragma unroll
        for (int q = 0; q < 2; q++) {
            *(uint4*)&Wh[srow * PSTR + shalf + q * 8] = pwh[q];
            *(uint4*)&Wl[srow * PSTR + shalf + q * 8] = pwl[q];
        }
        __syncthreads();

        if (kc < 7) {
            const int kb = (kc + 1) << 5;
            #pragma unroll
            for (int q = 0; q < 4; q++) pa[q] = *(const float4*)(Ag + kb + q * 4);
            #pragma unroll
            for (int q = 0; q < 2; q++) {
                pwh[q] = *(const uint4*)(WhG + kb + q * 8);
                pwl[q] = *(const uint4*)(WlG + kb + q * 8);
            }
        }

        #pragma unroll
        for (int ks = 0; ks < 32; ks += 16) {
            uint32_t ah[4][4], al[4][4], wh[4][2], wl[4][2];
            #pragma unroll
            for (int fm = 0; fm < 4; fm++) {
                const int r0 = ((wm << 6) + (fm << 4) + gid) * PSTR + ks + (tg << 1);
                ah[fm][0] = *(const uint32_t*)&Ah[r0];
                ah[fm][1] = *(const uint32_t*)&Ah[r0 + 8 * PSTR];
                ah[fm][2] = *(const uint32_t*)&Ah[r0 + 8];
                ah[fm][3] = *(const uint32_t*)&Ah[r0 + 8 * PSTR + 8];
                al[fm][0] = *(const uint32_t*)&Al[r0];
                al[fm][1] = *(const uint32_t*)&Al[r0 + 8 * PSTR];
                al[fm][2] = *(const uint32_t*)&Al[r0 + 8];
                al[fm][3] = *(const uint32_t*)&Al[r0 + 8 * PSTR + 8];
            }
            #pragma unroll
            for (int fn = 0; fn < 4; fn++) {
                const int nb = ((wn << 5) + (fn << 3) + gid) * PSTR + ks + (tg << 1);
                wh[fn][0] = *(const uint32_t*)&Wh[nb];
                wh[fn][1] = *(const uint32_t*)&Wh[nb + 8];
                wl[fn][0] = *(const uint32_t*)&Wl[nb];
                wl[fn][1] = *(const uint32_t*)&Wl[nb + 8];
            }
            #pragma unroll
            for (int fm = 0; fm < 4; fm++)
                #pragma unroll
                for (int fn = 0; fn < 4; fn++) {
                    mma_bf16(acc[fm][fn], ah[fm], wh[fn]);
                    mma_bf16(acc[fm][fn], ah[fm], wl[fn]);
                    mma_bf16(acc[fm][fn], al[fm], wh[fn]);
                }
        }
        __syncthreads();
    }

    #pragma unroll
    for (int fm = 0; fm < 4; fm++) {
        const int row = m0 + (wm << 6) + (fm << 4) + gid;
        #pragma unroll
        for (int fn = 0; fn < 4; fn++) {
            const int colL = (wn << 5) + (fn << 3) + (tg << 1);
            const float2 bv = *(const float2*)&bs[colL];
            const float* c = acc[fm][fn];
            float* Cp = C + (size_t)row * H + n0 + colL;
            *(float2*)Cp = make_float2(c[0] + bv.x, c[1] + bv.y);
            *(float2*)(Cp + 8 * H) = make_float2(c[2] + bv.x, c[3] + bv.y);
        }
    }
}

// ---------------------------------------------------------------------------
// HMMA recurrence: diagonal chains (m16), cluster-2, W_hh bf16 hi/lo resident
// in SMEM, state published as bf16 hi/lo (own SMEM + peer DSMEM), bf16x3 MMA.
// grid (2, 64), cluster (2,1,1), 256 threads (8 warps, n16 each).
// ---------------------------------------------------------------------------
struct RP {
    const float* W;
    const float* pre; long p_sb, p_sstep, p_sj;
    float*       out; long o_sb, o_sstep, o_sj;
    int diag;
};

constexpr int WSTR = 264;                             // bf16 row stride
constexpr int OFF_WL  = 128 * WSTR * 2;               // 67584
constexpr int OFF_AH0 = 2 * OFF_WL;                   // 135168
constexpr int APLANE  = 16 * WSTR * 2;                // 8448
constexpr int OFF_AL0 = OFF_AH0 + APLANE;
constexpr int OFF_AH1 = OFF_AL0 + APLANE;
constexpr int OFF_AL1 = OFF_AH1 + APLANE;
constexpr int RECUR3_SMEM = OFF_AL1 + APLANE;         // 168960 B

__global__ void __launch_bounds__(256, 1) __cluster_dims__(2, 1, 1)
recur3(RP X, RP Y)
{
    extern __shared__ char smx[];
    __nv_bfloat16* Wh = (__nv_bfloat16*)(smx);
    __nv_bfloat16* Wl = (__nv_bfloat16*)(smx + OFF_WL);
    __nv_bfloat16* AhB[2] = { (__nv_bfloat16*)(smx + OFF_AH0),
                              (__nv_bfloat16*)(smx + OFF_AH1) };
    __nv_bfloat16* AlB[2] = { (__nv_bfloat16*)(smx + OFF_AL0),
                              (__nv_bfloat16*)(smx + OFF_AL1) };
    const uint32_t planeH[2] = { OFF_AH0, OFF_AH1 };
    const uint32_t planeL[2] = { OFF_AL0, OFF_AL1 };

    const int rank  = blockIdx.x;
    const int clid  = blockIdx.y;
    const int path  = clid >> 5;
    const RP  P     = path ? Y : X;
    const int grp   = clid & 31;
    const int b     = grp >> 3;
    const int dbase = (grp & 7) << 4;

    const int tid  = threadIdx.x;
    const int wid  = tid >> 5;          // warp 0..7, n16 each
    const int lane = tid & 31;
    const int gid  = lane >> 2;
    const int tg   = lane & 3;

    // ---- fill W_hh hi/lo (rows = local cols of this rank) ----
    {
        const float* Wg = P.W + (size_t)(rank << 7) * H;
        for (int idx = tid; idx < 128 * 64; idx += 256) {
            int n = idx >> 6, kq = (idx & 63) << 2;
            float4 v = *(const float4*)&Wg[(size_t)n * H + kq];
            __nv_bfloat16 h0 = __float2bfloat16_rn(v.x);
            __nv_bfloat16 h1 = __float2bfloat16_rn(v.y);
            __nv_bfloat16 h2 = __float2bfloat16_rn(v.z);
            __nv_bfloat16 h3 = __float2bfloat16_rn(v.w);
            uint2 uh, ul;
            uh.x = ((uint32_t)__bfloat16_as_ushort(h1) << 16) | __bfloat16_as_ushort(h0);
            uh.y = ((uint32_t)__bfloat16_as_ushort(h3) << 16) | __bfloat16_as_ushort(h2);
            ul.x = ((uint32_t)__bfloat16_as_ushort(
                        __float2bfloat16_rn(v.y - __bfloat162float(h1))) << 16)
                 | __bfloat16_as_ushort(__float2bfloat16_rn(v.x - __bfloat162float(h0)));
            ul.y = ((uint32_t)__bfloat16_as_ushort(
                        __float2bfloat16_rn(v.w - __bfloat162float(h3))) << 16)
                 | __bfloat16_as_ushort(__float2bfloat16_rn(v.z - __bfloat162float(h2)));
            *(uint2*)&Wh[n * WSTR + kq] = uh;
            *(uint2*)&Wl[n * WSTR + kq] = ul;
        }
    }

    const uint32_t peerBase = mapa_u32(smem_u32(smx), rank ^ 1);

    // chains (m): cm0 = gid, cm1 = gid+8; cols (n): per nfrag f
    const int gc0 = (rank << 7) + (wid << 4) + (tg << 1);   // f=0 col; f=1 -> +8
    int jc0 = dbase + gid;
    int jc1 = dbase + gid + 8;

    // pre prefetch for st=0
    float2 pv[2][2];
    #pragma unroll
    for (int f = 0; f < 2; f++) {
        pv[0][f] = *(const float2*)(P.pre + b * P.p_sb + jc0 * P.p_sj + gc0 + (f << 3));
        pv[1][f] = *(const float2*)(P.pre + b * P.p_sb + jc1 * P.p_sj + gc0 + (f << 3));
    }

    const int kOwn  = rank << 3;          // own k-steps (8 of 16)
    const int kPeer = (rank ^ 1) << 3;
    const int aoff  = gid * WSTR + (tg << 1);

    __syncthreads();   // W ready

    for (int st = 0; st < 128; st++) {
        float acc[2][4] = {};

        if (st > 0) {
            const int rd = (st & 1) ? 1 : 0;
            const __nv_bfloat16* Acl = AlB[rd];
            const __nv_bfloat16* Ach = AhB[rd];
            #pragma unroll
            for (int half = 0; half < 2; half++) {
                const int kb = half ? kPeer : kOwn;
                if (half) CLUSTER_WAIT();
                #pragma unroll
                for (int ks8 = 0; ks8 < 8; ks8++) {
                    const int kk = (kb + ks8) << 4;
                    const __nv_bfloat16* ap = Ach + aoff + kk;
                    const __nv_bfloat16* alp = Acl + aoff + kk;
                    uint32_t ah[4], al[4];
                    ah[0] = *(const uint32_t*)ap;
                    ah[1] = *(const uint32_t*)(ap + 8 * WSTR);
                    ah[2] = *(const uint32_t*)(ap + 8);
                    ah[3] = *(const uint32_t*)(ap + 8 * WSTR + 8);
                    al[0] = *(const uint32_t*)alp;
                    al[1] = *(const uint32_t*)(alp + 8 * WSTR);
                    al[2] = *(const uint32_t*)(alp + 8);
                    al[3] = *(const uint32_t*)(alp + 8 * WSTR + 8);
                    #pragma unroll
                    for (int f = 0; f < 2; f++) {
                        const int nrow = (wid << 4) + (f << 3) + gid;
                        const __nv_bfloat16* wp = Wh + nrow * WSTR + (tg << 1) + kk;
                        const __nv_bfloat16* lp = Wl + nrow * WSTR + (tg << 1) + kk;
                        uint32_t wh[2] = { *(const uint32_t*)wp, *(const uint32_t*)(wp + 8) };
                        uint32_t wl2[2] = { *(const uint32_t*)lp, *(const uint32_t*)(lp + 8) };
                        mma_bf16(acc[f], ah, wh);
                        mma_bf16(acc[f], ah, wl2);
                        mma_bf16(acc[f], al, wh);
                    }
                }
            }
        }

        // epilogue: tanh(acc + pre).  acc[f]: c0,c1 = chain gid; c2,c3 = gid+8
        float h0[2][2], h1[2][2];
        #pragma unroll
        for (int f = 0; f < 2; f++) {
            h0[f][0] = my_tanh(acc[f][0] + pv[0][f].x);
            h0[f][1] = my_tanh(acc[f][1] + pv[0][f].y);
            h1[f][0] = my_tanh(acc[f][2] + pv[1][f].x);
            h1[f][1] = my_tanh(acc[f][3] + pv[1][f].y);
        }

        if (st < 127) {
            // publish state h(st) as bf16 hi/lo: own SMEM + peer DSMEM
            const int wbuf = (st & 1) ? 0 : 1;
            __nv_bfloat16* Anh = AhB[wbuf];
            __nv_bfloat16* Anl = AlB[wbuf];
            const uint32_t pH = peerBase + planeH[wbuf];
            const uint32_t pL = peerBase + planeL[wbuf];
            #pragma unroll
            for (int f = 0; f < 2; f++) {
                const int gcf = gc0 + (f << 3);
                const int o0 = gid * WSTR + gcf;
                const int o1 = (gid + 8) * WSTR + gcf;
                uint32_t hi0 = pack_bf16x2(h0[f][0], h0[f][1]);
                uint32_t hi1 = pack_bf16x2(h1[f][0], h1[f][1]);
                float r00 = h0[f][0] - __bfloat162float(__float2bfloat16_rn(h0[f][0]));
                float r01 = h0[f][1] - __bfloat162float(__float2bfloat16_rn(h0[f][1]));
                float r10 = h1[f][0] - __bfloat162float(__float2bfloat16_rn(h1[f][0]));
                float r11 = h1[f][1] - __bfloat162float(__float2bfloat16_rn(h1[f][1]));
                uint32_t lo0 = pack_bf16x2(r00, r01);
                uint32_t lo1 = pack_bf16x2(r10, r11);
                *(uint32_t*)&Anh[o0] = hi0;  *(uint32_t*)&Anh[o1] = hi1;
                *(uint32_t*)&Anl[o0] = lo0;  *(uint32_t*)&Anl[o1] = lo1;
                st_cluster_b32(pH + (uint32_t)o0 * 2, hi0);
                st_cluster_b32(pH + (uint32_t)o1 * 2, hi1);
                st_cluster_b32(pL + (uint32_t)o0 * 2, lo0);
                st_cluster_b32(pL + (uint32_t)o1 * 2, lo1);
            }
            __syncthreads();
            CLUSTER_ARRIVE();
        }

        // global output (fp32, full precision) inside the arrive->wait window
        #pragma unroll
        for (int f = 0; f < 2; f++) {
            const int gcf = gc0 + (f << 3);
            float* op0 = P.out + b * P.o_sb + st * P.o_sstep + jc0 * P.o_sj + gcf;
            float* op1 = P.out + b * P.o_sb + st * P.o_sstep + jc1 * P.o_sj + gcf;
            *(float2*)op0 = make_float2(h0[f][0], h0[f][1]);
            *(float2*)op1 = make_float2(h1[f][0], h1[f][1]);
        }

        if (st < 127) {
            if (P.diag) { jc0 = (jc0 + 1) & 127; jc1 = (jc1 + 1) & 127; }
            #pragma unroll
            for (int f = 0; f < 2; f++) {
                pv[0][f] = *(const float2*)(P.pre + b * P.p_sb + (st + 1) * P.p_sstep
                                            + jc0 * P.p_sj + gc0 + (f << 3));
                pv[1][f] = *(const float2*)(P.pre + b * P.p_sb + (st + 1) * P.p_sstep
                                            + jc1 * P.p_sj + gc0 + (f << 3));
            }
        }
    }
}

// ---------------------------------------------------------------------------
// Host orchestration: 2 W-split + 3 x (2 prepass + 1 recurrence) launches.
// ---------------------------------------------------------------------------
extern "C" void kernel_launch(void* const* d_in, const int* in_sizes, int n_in,
                              void* d_out, int out_size)
{
    const float* src   = (const float*)d_in[0];
    const float* trg   = (const float*)d_in[1];
    const float* Wx_ih = (const float*)d_in[2];
    const float* Wx_hh = (const float*)d_in[3];
    const float* bx_ih = (const float*)d_in[4];
    const float* bx_hh = (const float*)d_in[5];
    const float* Wy_ih = (const float*)d_in[6];
    const float* Wy_hh = (const float*)d_in[7];
    const float* by_ih = (const float*)d_in[8];
    const float* by_hh = (const float*)d_in[9];
    float* out = (float*)d_out;

    float *pre_x, *pre_y, *hx, *hy, *psx, *psy;
    __nv_bfloat16 *wxh, *wxl, *wyh, *wyl;
    cudaGetSymbolAddress((void**)&pre_x, g_pre_x);
    cudaGetSymbolAddress((void**)&pre_y, g_pre_y);
    cudaGetSymbolAddress((void**)&hx,    g_hx);
    cudaGetSymbolAddress((void**)&hy,    g_hy);
    cudaGetSymbolAddress((void**)&psx,   g_psx);
    cudaGetSymbolAddress((void**)&psy,   g_psy);
    cudaGetSymbolAddress((void**)&wxh,   g_wxh);
    cudaGetSymbolAddress((void**)&wxl,   g_wxl);
    cudaGetSymbolAddress((void**)&wyh,   g_wyh);
    cudaGetSymbolAddress((void**)&wyl,   g_wyl);

    cudaFuncSetAttribute(recur3,
                         cudaFuncAttributeMaxDynamicSharedMemorySize, RECUR3_SMEM);

    const int nW = 3 * 256 * 256;
    conv_w<<<(nW + 255) / 256, 256>>>(Wx_ih, wxh, wxl, nW);
    conv_w<<<(nW + 255) / 256, 256>>>(Wy_ih, wyh, wyl, nW);

    for (int d = 0; d < 3; d++) {
        const int woff = d * 256 * 256;
        if (d == 0) {
            hmma_prepass<<<dim3(B * S / 128, 2), 256>>>(
                src, wxh + woff, wxl + woff, bx_ih, bx_hh, psx);
            hmma_prepass<<<dim3(B * T / 128, 2), 256>>>(
                trg, wyh + woff, wyl + woff, by_ih, by_hh, psy);
        } else {
            hmma_prepass<<<dim3(B * S * T / 128, 2), 256>>>(
                hx, wxh + woff, wxl + woff, bx_ih + d * H, bx_hh + d * H, pre_x);
            hmma_prepass<<<dim3(B * S * T / 128, 2), 256>>>(
                hy, wyh + woff, wyl + woff, by_ih + d * H, by_hh + d * H, pre_y);
        }

        const long OS = (d == 2) ? 2 * H : H;
        float* Ox = (d == 2) ? out     : hx;
        float* Oy = (d == 2) ? out + H : hy;

        RP X, Y;
        X.W = Wx_hh + (size_t)d * H * H;  X.diag = 1;
        X.out = Ox; X.o_sb = (long)S * T * OS; X.o_sstep = (long)T * OS; X.o_sj = OS;
        if (d == 0) { X.pre = psx;   X.p_sb = (long)S * H;     X.p_sstep = H;           X.p_sj = 0; }
        else        { X.pre = pre_x; X.p_sb = (long)S * T * H; X.p_sstep = (long)T * H; X.p_sj = H; }

        Y.W = Wy_hh + (size_t)d * H * H;  Y.diag = 0;
        Y.out = Oy; Y.o_sb = (long)S * T * OS; Y.o_sstep = OS; Y.o_sj = (long)T * OS;
        if (d == 0) { Y.pre = psy;   Y.p_sb = (long)T * H;     Y.p_sstep = H; Y.p_sj = 0; }
        else        { Y.pre = pre_y; Y.p_sb = (long)S * T * H; Y.p_sstep = H; Y.p_sj = (long)T * H; }

        recur3<<<dim3(2, 64), 256, RECUR3_SMEM>>>(X, Y);
    }
}

// round 14
// speedup vs baseline: 2.0595x; 1.1811x over previous
#include <cuda_runtime.h>
#include <cuda_bf16.h>
#include <math.h>
#include <stdint.h>

constexpr int H = 256;
constexpr int B = 4;
constexpr int S = 128;
constexpr int T = 128;

typedef unsigned long long ull;

// Scratch (device globals — no allocation allowed)
__device__ float g_pre_x[(size_t)B * S * T * H];
__device__ float g_pre_y[(size_t)B * S * T * H];
__device__ float g_hx  [(size_t)B * S * T * H];
__device__ float g_hy  [(size_t)B * S * T * H];
__device__ float g_psx [(size_t)B * S * H];
__device__ float g_psy [(size_t)B * T * H];
// bf16 hi/lo splits of the 3-depth ih-weights (x and y paths)
__device__ __nv_bfloat16 g_wxh[3 * 256 * 256];
__device__ __nv_bfloat16 g_wxl[3 * 256 * 256];
__device__ __nv_bfloat16 g_wyh[3 * 256 * 256];
__device__ __nv_bfloat16 g_wyl[3 * 256 * 256];

// ---------------- PTX helpers ----------------
__device__ __forceinline__ uint32_t smem_u32(const void* p) {
    uint32_t a;
    asm("{ .reg .u64 t; cvta.to.shared.u64 t, %1; cvt.u32.u64 %0, t; }" : "=r"(a) : "l"(p));
    return a;
}
__device__ __forceinline__ uint32_t mapa_u32(uint32_t addr, uint32_t rank) {
    uint32_t r;
    asm("mapa.shared::cluster.u32 %0, %1, %2;" : "=r"(r) : "r"(addr), "r"(rank));
    return r;
}
__device__ __forceinline__ void st_cluster_b32(uint32_t addr, uint32_t v) {
    asm volatile("st.shared::cluster.b32 [%0], %1;" :: "r"(addr), "r"(v) : "memory");
}
#define CLUSTER_ARRIVE() asm volatile("barrier.cluster.arrive.aligned;" ::: "memory")
#define CLUSTER_WAIT()   asm volatile("barrier.cluster.wait.aligned;" ::: "memory")

// Accurate-enough fast tanh (MUFU path forced; err ~1e-6, budget 1e-3)
__device__ __forceinline__ float my_tanh(float x) {
    float ax = fabsf(x);
    float e  = __expf(-2.0f * ax);
    float t  = __fdividef(1.0f - e, 1.0f + e);
    return x < 0.0f ? -t : t;
}

// bf16 MMA m16n8k16, fp32 accumulate (sm_80-era HMMA — compiles on compute_103)
__device__ __forceinline__ void mma_bf16(float* c, const uint32_t* a, const uint32_t* b) {
    asm volatile(
        "mma.sync.aligned.m16n8k16.row.col.f32.bf16.bf16.f32 "
        "{%0,%1,%2,%3}, {%4,%5,%6,%7}, {%8,%9}, {%0,%1,%2,%3};"
        : "+f"(c[0]), "+f"(c[1]), "+f"(c[2]), "+f"(c[3])
        : "r"(a[0]), "r"(a[1]), "r"(a[2]), "r"(a[3]), "r"(b[0]), "r"(b[1]));
}

__device__ __forceinline__ uint32_t pack_bf16x2(float a, float b) {
    return ((uint32_t)__bfloat16_as_ushort(__float2bfloat16_rn(b)) << 16)
         | __bfloat16_as_ushort(__float2bfloat16_rn(a));
}

// ---------------------------------------------------------------------------
// W split kernel: fp32 -> (hi, lo) bf16 pair.  lo = bf16(v - float(hi)).
// ---------------------------------------------------------------------------
__global__ void conv_w(const float* __restrict__ W,
                       __nv_bfloat16* __restrict__ hi,
                       __nv_bfloat16* __restrict__ lo, int n)
{
    int i = blockIdx.x * 256 + threadIdx.x;
    if (i < n) {
        float v = W[i];
        __nv_bfloat16 h = __float2bfloat16_rn(v);
        hi[i] = h;
        lo[i] = __float2bfloat16_rn(v - __bfloat162float(h));
    }
}

// ---------------------------------------------------------------------------
// HMMA prepass (UNCHANGED structure from R12/13, passing): C = A W^T + b1+b2.
// ---------------------------------------------------------------------------
constexpr int PSTR = 40;   // smem row stride in bf16

__global__ void __launch_bounds__(256, 1) hmma_prepass(
    const float* __restrict__ A,
    const __nv_bfloat16* __restrict__ Whi, const __nv_bfloat16* __restrict__ Wlo,
    const float* __restrict__ b1, const float* __restrict__ b2,
    float* __restrict__ C)
{
    __shared__ __nv_bfloat16 Ah[128 * PSTR], Al[128 * PSTR];
    __shared__ __nv_bfloat16 Wh[128 * PSTR], Wl[128 * PSTR];
    __shared__ float bs[128];

    const int m0  = blockIdx.x << 7;
    const int n0  = blockIdx.y << 7;
    const int tid = threadIdx.x;
    const int wid = tid >> 5;
    const int lane = tid & 31;
    const int gid = lane >> 2;
    const int tg  = lane & 3;
    const int wm  = wid >> 2;
    const int wn  = wid & 3;

    if (tid < 128) bs[tid] = b1[n0 + tid] + b2[n0 + tid];

    const int srow = tid >> 1;
    const int shalf = (tid & 1) << 4;
    const float* Ag = A + (size_t)(m0 + srow) * H + shalf;
    const __nv_bfloat16* WhG = Whi + (size_t)(n0 + srow) * H + shalf;
    const __nv_bfloat16* WlG = Wlo + (size_t)(n0 + srow) * H + shalf;

    float4 pa[4];
    uint4  pwh[2], pwl[2];
    #pragma unroll
    for (int q = 0; q < 4; q++) pa[q] = *(const float4*)(Ag + q * 4);
    #pragma unroll
    for (int q = 0; q < 2; q++) {
        pwh[q] = *(const uint4*)(WhG + q * 8);
        pwl[q] = *(const uint4*)(WlG + q * 8);
    }

    float acc[4][4][4] = {};

    for (int kc = 0; kc < 8; kc++) {
        #pragma unroll
        for (int q = 0; q < 4; q++) {
            float4 v = pa[q];
            __nv_bfloat16 h0 = __float2bfloat16_rn(v.x);
            __nv_bfloat16 h1 = __float2bfloat16_rn(v.y);
            __nv_bfloat16 h2 = __float2bfloat16_rn(v.z);
            __nv_bfloat16 h3 = __float2bfloat16_rn(v.w);
            uint2 uh, ul;
            uh.x = ((uint32_t)__bfloat16_as_ushort(h1) << 16) | __bfloat16_as_ushort(h0);
            uh.y = ((uint32_t)__bfloat16_as_ushort(h3) << 16) | __bfloat16_as_ushort(h2);
            __nv_bfloat16 l0 = __float2bfloat16_rn(v.x - __bfloat162float(h0));
            __nv_bfloat16 l1 = __float2bfloat16_rn(v.y - __bfloat162float(h1));
            __nv_bfloat16 l2 = __float2bfloat16_rn(v.z - __bfloat162float(h2));
            __nv_bfloat16 l3 = __float2bfloat16_rn(v.w - __bfloat162float(h3));
            ul.x = ((uint32_t)__bfloat16_as_ushort(l1) << 16) | __bfloat16_as_ushort(l0);
            ul.y = ((uint32_t)__bfloat16_as_ushort(l3) << 16) | __bfloat16_as_ushort(l2);
            *(uint2*)&Ah[srow * PSTR + shalf + q * 4] = uh;
            *(uint2*)&Al[srow * PSTR + shalf + q * 4] = ul;
        }
        #pragma unroll
        for (int q = 0; q < 2; q++) {
            *(uint4*)&Wh[srow * PSTR + shalf + q * 8] = pwh[q];
            *(uint4*)&Wl[srow * PSTR + shalf + q * 8] = pwl[q];
        }
        __syncthreads();

        if (kc < 7) {
            const int kb = (kc + 1) << 5;
            #pragma unroll
            for (int q = 0; q < 4; q++) pa[q] = *(const float4*)(Ag + kb + q * 4);
            #pragma unroll
            for (int q = 0; q < 2; q++) {
                pwh[q] = *(const uint4*)(WhG + kb + q * 8);
                pwl[q] = *(const uint4*)(WlG + kb + q * 8);
            }
        }

        #pragma unroll
        for (int ks = 0; ks < 32; ks += 16) {
            uint32_t ah[4][4], al[4][4], wh[4][2], wl[4][2];
            #pragma unroll
            for (int fm = 0; fm < 4; fm++) {
                const int r0 = ((wm << 6) + (fm << 4) + gid) * PSTR + ks + (tg << 1);
                ah[fm][0] = *(const uint32_t*)&Ah[r0];
                ah[fm][1] = *(const uint32_t*)&Ah[r0 + 8 * PSTR];
                ah[fm][2] = *(const uint32_t*)&Ah[r0 + 8];
                ah[fm][3] = *(const uint32_t*)&Ah[r0 + 8 * PSTR + 8];
                al[fm][0] = *(const uint32_t*)&Al[r0];
                al[fm][1] = *(const uint32_t*)&Al[r0 + 8 * PSTR];
                al[fm][2] = *(const uint32_t*)&Al[r0 + 8];
                al[fm][3] = *(const uint32_t*)&Al[r0 + 8 * PSTR + 8];
            }
            #pragma unroll
            for (int fn = 0; fn < 4; fn++) {
                const int nb = ((wn << 5) + (fn << 3) + gid) * PSTR + ks + (tg << 1);
                wh[fn][0] = *(const uint32_t*)&Wh[nb];
                wh[fn][1] = *(const uint32_t*)&Wh[nb + 8];
                wl[fn][0] = *(const uint32_t*)&Wl[nb];
                wl[fn][1] = *(const uint32_t*)&Wl[nb + 8];
            }
            #pragma unroll
            for (int fm = 0; fm < 4; fm++)
                #pragma unroll
                for (int fn = 0; fn < 4; fn++) {
                    mma_bf16(acc[fm][fn], ah[fm], wh[fn]);
                    mma_bf16(acc[fm][fn], ah[fm], wl[fn]);
                    mma_bf16(acc[fm][fn], al[fm], wh[fn]);
                }
        }
        __syncthreads();
    }

    #pragma unroll
    for (int fm = 0; fm < 4; fm++) {
        const int row = m0 + (wm << 6) + (fm << 4) + gid;
        #pragma unroll
        for (int fn = 0; fn < 4; fn++) {
            const int colL = (wn << 5) + (fn << 3) + (tg << 1);
            const float2 bv = *(const float2*)&bs[colL];
            const float* c = acc[fm][fn];
            float* Cp = C + (size_t)row * H + n0 + colL;
            *(float2*)Cp = make_float2(c[0] + bv.x, c[1] + bv.y);
            *(float2*)(Cp + 8 * H) = make_float2(c[2] + bv.x, c[3] + bv.y);
        }
    }
}

// ---------------------------------------------------------------------------
// HMMA recurrence v2: W_hh fragments hoisted to REGISTERS (128 u32/warp) for
// the whole depth — zero W LDS traffic in the step loop.  Fragments stored
// own-half-first (q = half*8 + s) so register indices stay compile-time.
// Diagonal chains (m16), cluster-2, state bf16 hi/lo via SMEM + peer DSMEM.
// grid (2, 64), cluster (2,1,1), 256 threads (8 warps, n16 each).
// ---------------------------------------------------------------------------
struct RP {
    const float* W;
    const float* pre; long p_sb, p_sstep, p_sj;
    float*       out; long o_sb, o_sstep, o_sj;
    int diag;
};

constexpr int WSTR = 264;                             // bf16 row stride
constexpr int OFF_WL  = 128 * WSTR * 2;               // 67584
constexpr int OFF_AH0 = 2 * OFF_WL;                   // 135168
constexpr int APLANE  = 16 * WSTR * 2;                // 8448
constexpr int OFF_AL0 = OFF_AH0 + APLANE;
constexpr int OFF_AH1 = OFF_AL0 + APLANE;
constexpr int OFF_AL1 = OFF_AH1 + APLANE;
constexpr int RECUR3_SMEM = OFF_AL1 + APLANE;         // 168960 B

__global__ void __launch_bounds__(256, 1) __cluster_dims__(2, 1, 1)
recur4(RP X, RP Y)
{
    extern __shared__ char smx[];
    __nv_bfloat16* Wh = (__nv_bfloat16*)(smx);
    __nv_bfloat16* Wl = (__nv_bfloat16*)(smx + OFF_WL);
    __nv_bfloat16* AhB[2] = { (__nv_bfloat16*)(smx + OFF_AH0),
                              (__nv_bfloat16*)(smx + OFF_AH1) };
    __nv_bfloat16* AlB[2] = { (__nv_bfloat16*)(smx + OFF_AL0),
                              (__nv_bfloat16*)(smx + OFF_AL1) };
    const uint32_t planeH[2] = { OFF_AH0, OFF_AH1 };
    const uint32_t planeL[2] = { OFF_AL0, OFF_AL1 };

    const int rank  = blockIdx.x;
    const int clid  = blockIdx.y;
    const int path  = clid >> 5;
    const RP  P     = path ? Y : X;
    const int grp   = clid & 31;
    const int b     = grp >> 3;
    const int dbase = (grp & 7) << 4;

    const int tid  = threadIdx.x;
    const int wid  = tid >> 5;          // warp 0..7, n16 each
    const int lane = tid & 31;
    const int gid  = lane >> 2;
    const int tg   = lane & 3;

    // ---- fill W_hh hi/lo SMEM (rows = local cols of this rank) ----
    {
        const float* Wg = P.W + (size_t)(rank << 7) * H;
        for (int idx = tid; idx < 128 * 64; idx += 256) {
            int n = idx >> 6, kq = (idx & 63) << 2;
            float4 v = *(const float4*)&Wg[(size_t)n * H + kq];
            __nv_bfloat16 h0 = __float2bfloat16_rn(v.x);
            __nv_bfloat16 h1 = __float2bfloat16_rn(v.y);
            __nv_bfloat16 h2 = __float2bfloat16_rn(v.z);
            __nv_bfloat16 h3 = __float2bfloat16_rn(v.w);
            uint2 uh, ul;
            uh.x = ((uint32_t)__bfloat16_as_ushort(h1) << 16) | __bfloat16_as_ushort(h0);
            uh.y = ((uint32_t)__bfloat16_as_ushort(h3) << 16) | __bfloat16_as_ushort(h2);
            ul.x = ((uint32_t)__bfloat16_as_ushort(
                        __float2bfloat16_rn(v.y - __bfloat162float(h1))) << 16)
                 | __bfloat16_as_ushort(__float2bfloat16_rn(v.x - __bfloat162float(h0)));
            ul.y = ((uint32_t)__bfloat16_as_ushort(
                        __float2bfloat16_rn(v.w - __bfloat162float(h3))) << 16)
                 | __bfloat16_as_ushort(__float2bfloat16_rn(v.z - __bfloat162float(h2)));
            *(uint2*)&Wh[n * WSTR + kq] = uh;
            *(uint2*)&Wl[n * WSTR + kq] = ul;
        }
    }

    const uint32_t peerBase = mapa_u32(smem_u32(smx), rank ^ 1);

    const int gc0 = (rank << 7) + (wid << 4) + (tg << 1);
    int jc0 = dbase + gid;
    int jc1 = dbase + gid + 8;

    float2 pv[2][2];
    #pragma unroll
    for (int f = 0; f < 2; f++) {
        pv[0][f] = *(const float2*)(P.pre + b * P.p_sb + jc0 * P.p_sj + gc0 + (f << 3));
        pv[1][f] = *(const float2*)(P.pre + b * P.p_sb + jc1 * P.p_sj + gc0 + (f << 3));
    }

    const int kOwn  = rank << 3;          // own-half k-steps (8 of 16)
    const int kPeer = (rank ^ 1) << 3;
    const int aoff  = gid * WSTR + (tg << 1);

    __syncthreads();   // W SMEM ready

    // ---- hoist W fragments to registers: wfr[f][q][0..1]=wh, [2..3]=wl ----
    // q = half*8 + s : own-half fragments first (register index compile-time;
    // only the load ADDRESS depends on rank).
    uint32_t wfr[2][16][4];
    #pragma unroll
    for (int half = 0; half < 2; half++) {
        const int kb = half ? kPeer : kOwn;
        #pragma unroll
        for (int s = 0; s < 8; s++) {
            const int kk = (kb + s) << 4;
            #pragma unroll
            for (int f = 0; f < 2; f++) {
                const int nrow = (wid << 4) + (f << 3) + gid;
                const __nv_bfloat16* wp = Wh + nrow * WSTR + (tg << 1) + kk;
                const __nv_bfloat16* lp = Wl + nrow * WSTR + (tg << 1) + kk;
                wfr[f][half * 8 + s][0] = *(const uint32_t*)wp;
                wfr[f][half * 8 + s][1] = *(const uint32_t*)(wp + 8);
                wfr[f][half * 8 + s][2] = *(const uint32_t*)lp;
                wfr[f][half * 8 + s][3] = *(const uint32_t*)(lp + 8);
            }
        }
    }

    for (int st = 0; st < 128; st++) {
        float acc[2][4] = {};

        if (st > 0) {
            const int rd = (st & 1) ? 1 : 0;
            const __nv_bfloat16* Acl = AlB[rd];
            const __nv_bfloat16* Ach = AhB[rd];
            #pragma unroll
            for (int half = 0; half < 2; half++) {
                const int kb = half ? kPeer : kOwn;
                if (half) CLUSTER_WAIT();
                #pragma unroll
                for (int s = 0; s < 8; s++) {
                    const int kk = (kb + s) << 4;
                    const __nv_bfloat16* ap  = Ach + aoff + kk;
                    const __nv_bfloat16* alp = Acl + aoff + kk;
                    uint32_t ah[4], al[4];
                    ah[0] = *(const uint32_t*)ap;
                    ah[1] = *(const uint32_t*)(ap + 8 * WSTR);
                    ah[2] = *(const uint32_t*)(ap + 8);
                    ah[3] = *(const uint32_t*)(ap + 8 * WSTR + 8);
                    al[0] = *(const uint32_t*)alp;
                    al[1] = *(const uint32_t*)(alp + 8 * WSTR);
                    al[2] = *(const uint32_t*)(alp + 8);
                    al[3] = *(const uint32_t*)(alp + 8 * WSTR + 8);
                    #pragma unroll
                    for (int f = 0; f < 2; f++) {
                        const uint32_t* wq = wfr[f][half * 8 + s];
                        mma_bf16(acc[f], ah, wq);        // ah * wh
                        mma_bf16(acc[f], ah, wq + 2);    // ah * wl
                        mma_bf16(acc[f], al, wq);        // al * wh
                    }
                }
            }
        }

        float h0[2][2], h1[2][2];
        #pragma unroll
        for (int f = 0; f < 2; f++) {
            h0[f][0] = my_tanh(acc[f][0] + pv[0][f].x);
            h0[f][1] = my_tanh(acc[f][1] + pv[0][f].y);
            h1[f][0] = my_tanh(acc[f][2] + pv[1][f].x);
            h1[f][1] = my_tanh(acc[f][3] + pv[1][f].y);
        }

        if (st < 127) {
            const int wbuf = (st & 1) ? 0 : 1;
            __nv_bfloat16* Anh = AhB[wbuf];
            __nv_bfloat16* Anl = AlB[wbuf];
            const uint32_t pH = peerBase + planeH[wbuf];
            const uint32_t pL = peerBase + planeL[wbuf];
            #pragma unroll
            for (int f = 0; f < 2; f++) {
                const int gcf = gc0 + (f << 3);
                const int o0 = gid * WSTR + gcf;
                const int o1 = (gid + 8) * WSTR + gcf;
                uint32_t hi0 = pack_bf16x2(h0[f][0], h0[f][1]);
                uint32_t hi1 = pack_bf16x2(h1[f][0], h1[f][1]);
                float r00 = h0[f][0] - __bfloat162float(__float2bfloat16_rn(h0[f][0]));
                float r01 = h0[f][1] - __bfloat162float(__float2bfloat16_rn(h0[f][1]));
                float r10 = h1[f][0] - __bfloat162float(__float2bfloat16_rn(h1[f][0]));
                float r11 = h1[f][1] - __bfloat162float(__float2bfloat16_rn(h1[f][1]));
                uint32_t lo0 = pack_bf16x2(r00, r01);
                uint32_t lo1 = pack_bf16x2(r10, r11);
                *(uint32_t*)&Anh[o0] = hi0;  *(uint32_t*)&Anh[o1] = hi1;
                *(uint32_t*)&Anl[o0] = lo0;  *(uint32_t*)&Anl[o1] = lo1;
                st_cluster_b32(pH + (uint32_t)o0 * 2, hi0);
                st_cluster_b32(pH + (uint32_t)o1 * 2, hi1);
                st_cluster_b32(pL + (uint32_t)o0 * 2, lo0);
                st_cluster_b32(pL + (uint32_t)o1 * 2, lo1);
            }
            __syncthreads();       // own stores visible CTA-wide (own-half read)
            CLUSTER_ARRIVE();      // releases DSMEM stores; matched by wait(st+1)
        }

        // global output (fp32) inside the arrive->wait window
        #pragma unroll
        for (int f = 0; f < 2; f++) {
            const int gcf = gc0 + (f << 3);
            float* op0 = P.out + b * P.o_sb + st * P.o_sstep + jc0 * P.o_sj + gcf;
            float* op1 = P.out + b * P.o_sb + st * P.o_sstep + jc1 * P.o_sj + gcf;
            *(float2*)op0 = make_float2(h0[f][0], h0[f][1]);
            *(float2*)op1 = make_float2(h1[f][0], h1[f][1]);
        }

        if (st < 127) {
            if (P.diag) { jc0 = (jc0 + 1) & 127; jc1 = (jc1 + 1) & 127; }
            #pragma unroll
            for (int f = 0; f < 2; f++) {
                pv[0][f] = *(const float2*)(P.pre + b * P.p_sb + (st + 1) * P.p_sstep
                                            + jc0 * P.p_sj + gc0 + (f << 3));
                pv[1][f] = *(const float2*)(P.pre + b * P.p_sb + (st + 1) * P.p_sstep
                                            + jc1 * P.p_sj + gc0 + (f << 3));
            }
        }
    }
}

// ---------------------------------------------------------------------------
// Host orchestration: 2 W-split + 3 x (2 prepass + 1 recurrence) launches.
// ---------------------------------------------------------------------------
extern "C" void kernel_launch(void* const* d_in, const int* in_sizes, int n_in,
                              void* d_out, int out_size)
{
    const float* src   = (const float*)d_in[0];
    const float* trg   = (const float*)d_in[1];
    const float* Wx_ih = (const float*)d_in[2];
    const float* Wx_hh = (const float*)d_in[3];
    const float* bx_ih = (const float*)d_in[4];
    const float* bx_hh = (const float*)d_in[5];
    const float* Wy_ih = (const float*)d_in[6];
    const float* Wy_hh = (const float*)d_in[7];
    const float* by_ih = (const float*)d_in[8];
    const float* by_hh = (const float*)d_in[9];
    float* out = (float*)d_out;

    float *pre_x, *pre_y, *hx, *hy, *psx, *psy;
    __nv_bfloat16 *wxh, *wxl, *wyh, *wyl;
    cudaGetSymbolAddress((void**)&pre_x, g_pre_x);
    cudaGetSymbolAddress((void**)&pre_y, g_pre_y);
    cudaGetSymbolAddress((void**)&hx,    g_hx);
    cudaGetSymbolAddress((void**)&hy,    g_hy);
    cudaGetSymbolAddress((void**)&psx,   g_psx);
    cudaGetSymbolAddress((void**)&psy,   g_psy);
    cudaGetSymbolAddress((void**)&wxh,   g_wxh);
    cudaGetSymbolAddress((void**)&wxl,   g_wxl);
    cudaGetSymbolAddress((void**)&wyh,   g_wyh);
    cudaGetSymbolAddress((void**)&wyl,   g_wyl);

    cudaFuncSetAttribute(recur4,
                         cudaFuncAttributeMaxDynamicSharedMemorySize, RECUR3_SMEM);

    const int nW = 3 * 256 * 256;
    conv_w<<<(nW + 255) / 256, 256>>>(Wx_ih, wxh, wxl, nW);
    conv_w<<<(nW + 255) / 256, 256>>>(Wy_ih, wyh, wyl, nW);

    for (int d = 0; d < 3; d++) {
        const int woff = d * 256 * 256;
        if (d == 0) {
            hmma_prepass<<<dim3(B * S / 128, 2), 256>>>(
                src, wxh + woff, wxl + woff, bx_ih, bx_hh, psx);
            hmma_prepass<<<dim3(B * T / 128, 2), 256>>>(
                trg, wyh + woff, wyl + woff, by_ih, by_hh, psy);
        } else {
            hmma_prepass<<<dim3(B * S * T / 128, 2), 256>>>(
                hx, wxh + woff, wxl + woff, bx_ih + d * H, bx_hh + d * H, pre_x);
            hmma_prepass<<<dim3(B * S * T / 128, 2), 256>>>(
                hy, wyh + woff, wyl + woff, by_ih + d * H, by_hh + d * H, pre_y);
        }

        const long OS = (d == 2) ? 2 * H : H;
        float* Ox = (d == 2) ? out     : hx;
        float* Oy = (d == 2) ? out + H : hy;

        RP X, Y;
        X.W = Wx_hh + (size_t)d * H * H;  X.diag = 1;
        X.out = Ox; X.o_sb = (long)S * T * OS; X.o_sstep = (long)T * OS; X.o_sj = OS;
        if (d == 0) { X.pre = psx;   X.p_sb = (long)S * H;     X.p_sstep = H;           X.p_sj = 0; }
        else        { X.pre = pre_x; X.p_sb = (long)S * T * H; X.p_sstep = (long)T * H; X.p_sj = H; }

        Y.W = Wy_hh + (size_t)d * H * H;  Y.diag = 0;
        Y.out = Oy; Y.o_sb = (long)S * T * OS; Y.o_sstep = OS; Y.o_sj = (long)T * OS;
        if (d == 0) { Y.pre = psy;   Y.p_sb = (long)T * H;     Y.p_sstep = H; Y.p_sj = 0; }
        else        { Y.pre = pre_y; Y.p_sb = (long)S * T * H; Y.p_sstep = H; Y.p_sj = (long)T * H; }

        recur4<<<dim3(2, 64), 256, RECUR3_SMEM>>>(X, Y);
    }
}